// round 13
// baseline (speedup 1.0000x reference)
#include <cuda_runtime.h>
#include <cuda_fp16.h>
#include <cstdint>
#include <stdint.h>
#include <math.h>

#define B_ 8
#define N_ 1024
#define C_ 768
#define H_ 12
#define DH_ 64
#define NIMG_ 784

// Scratch (static device arrays: allocation-free per harness rules)
__device__ float  g_qkv[B_ * N_ * 3 * C_];      // qkv output (f32)
__device__ float  g_q[B_ * H_ * N_ * DH_];      // [bh][n][d] f32
__device__ float  g_k[B_ * H_ * N_ * DH_];
__device__ float  g_v[B_ * H_ * N_ * DH_];
__device__ __half gh_x[B_ * N_ * C_];           // x_t fp16
__device__ __half gh_qkvw[3 * C_ * C_];         // qkv_w fp16
__device__ __half gh_projw[C_ * C_];            // proj_w fp16
__device__ __half g_aoh[B_ * N_ * C_];          // attention out fp16

__device__ __forceinline__ unsigned packh2(float a, float b) {
    __half2 h = __floats2half2_rn(a, b);
    return *(unsigned*)&h;
}

__device__ __forceinline__ void mma_f16(float* d, const unsigned* a, const unsigned* b) {
    asm volatile(
        "mma.sync.aligned.m16n8k16.row.col.f32.f16.f16.f32 "
        "{%0,%1,%2,%3}, {%4,%5,%6,%7}, {%8,%9}, {%0,%1,%2,%3};"
        : "+f"(d[0]), "+f"(d[1]), "+f"(d[2]), "+f"(d[3])
        : "r"(a[0]), "r"(a[1]), "r"(a[2]), "r"(a[3]), "r"(b[0]), "r"(b[1]));
}

__device__ __forceinline__ unsigned sptr(const void* p) {
    return (unsigned)__cvta_generic_to_shared(p);
}

__device__ __forceinline__ void ldsm_x4(unsigned& r0, unsigned& r1,
                                        unsigned& r2, unsigned& r3, unsigned addr) {
    asm volatile("ldmatrix.sync.aligned.m8n8.x4.shared.b16 {%0,%1,%2,%3}, [%4];"
        : "=r"(r0), "=r"(r1), "=r"(r2), "=r"(r3) : "r"(addr));
}

// ---------------------------------------------------------------------------
// f32 -> f16 elementwise (8 elements/thread)
// ---------------------------------------------------------------------------
__global__ void f2h_kernel(const float* __restrict__ in, __half* __restrict__ out, int n8)
{
    int i = blockIdx.x * blockDim.x + threadIdx.x;
    if (i >= n8) return;
    float4 a = ((const float4*)in)[i * 2];
    float4 b = ((const float4*)in)[i * 2 + 1];
    uint4 u;
    u.x = packh2(a.x, a.y); u.y = packh2(a.z, a.w);
    u.z = packh2(b.x, b.y); u.w = packh2(b.z, b.w);
    ((uint4*)out)[i] = u;
}

// ---------------------------------------------------------------------------
// FP16-input GEMM, fat warp tiles: block 128x128, BK=32, 128 threads =
// 4 warps (2m x 2n), warp tile 64x64 -> per ks: 8 LDSM.x4 feed 32 MMAs.
// Double-buffered smem, 1 barrier/iter. fp32 accumulate.
// ---------------------------------------------------------------------------
#define BKh 32
#define SSTRH 40
#define TILE_H (128 * SSTRH)

template <bool HALF_OUT>
__global__ void __launch_bounds__(128, 2) gemm_h(
    const __half* __restrict__ A, const __half* __restrict__ W,
    const float* __restrict__ bias, void* __restrict__ outv,
    int M, int Nout, int K)
{
    __shared__ __align__(16) __half sA[2][TILE_H];
    __shared__ __align__(16) __half sB[2][TILE_H];

    const int t = threadIdx.x;
    const int lane = t & 31;
    const int warp = t >> 5;
    const int wm = (warp & 1) * 64;
    const int wn = (warp >> 1) * 64;
    const int m0 = blockIdx.y * 128;
    const int n0 = blockIdx.x * 128;

    // loader: 128 rows x 32 halves per matrix = 512 uint4; 4 per thread
    int rg[4], cg[4];
#pragma unroll
    for (int i = 0; i < 4; i++) { rg[i] = (t + i * 128) >> 2; cg[i] = ((t + i * 128) & 3) * 8; }

    const int lg = lane >> 3, lr = lane & 7;
    const int a_off = ((lg & 1) * 8 + lr) * SSTRH + (lg >> 1) * 8;
    const int b_off = ((lg >> 1) * 8 + lr) * SSTRH + (lg & 1) * 8;

    float acc[4][8][4];
#pragma unroll
    for (int i = 0; i < 4; i++)
#pragma unroll
        for (int j = 0; j < 8; j++)
#pragma unroll
            for (int v = 0; v < 4; v++) acc[i][j][v] = 0.f;

    const int fr = lane >> 2;
    const int fc = lane & 3;

    uint4 qa[4], qb[4];
#pragma unroll
    for (int i = 0; i < 4; i++) {
        qa[i] = *(const uint4*)(A + (size_t)(m0 + rg[i]) * K + cg[i]);
        qb[i] = *(const uint4*)(W + (size_t)(n0 + rg[i]) * K + cg[i]);
    }
#pragma unroll
    for (int i = 0; i < 4; i++) {
        *(uint4*)&sA[0][rg[i] * SSTRH + cg[i]] = qa[i];
        *(uint4*)&sB[0][rg[i] * SSTRH + cg[i]] = qb[i];
    }
    __syncthreads();

    const int nIter = K / BKh;
    for (int it = 0; it < nIter; it++) {
        const int buf = it & 1;
        const bool has_next = (it + 1) < nIter;

        if (has_next) {
            int kn = (it + 1) * BKh;
#pragma unroll
            for (int i = 0; i < 4; i++) {
                qa[i] = *(const uint4*)(A + (size_t)(m0 + rg[i]) * K + kn + cg[i]);
                qb[i] = *(const uint4*)(W + (size_t)(n0 + rg[i]) * K + kn + cg[i]);
            }
        }

        const __half* cA = sA[buf];
        const __half* cB = sB[buf];
#pragma unroll
        for (int ks = 0; ks < 2; ks++) {
            unsigned areg[4][4], breg[8][2];
#pragma unroll
            for (int mf = 0; mf < 4; mf++)
                ldsm_x4(areg[mf][0], areg[mf][1], areg[mf][2], areg[mf][3],
                        sptr(cA + (wm + mf * 16) * SSTRH + ks * 16 + a_off));
#pragma unroll
            for (int np = 0; np < 4; np++)
                ldsm_x4(breg[np * 2][0], breg[np * 2][1],
                        breg[np * 2 + 1][0], breg[np * 2 + 1][1],
                        sptr(cB + (wn + np * 16) * SSTRH + ks * 16 + b_off));
#pragma unroll
            for (int mf = 0; mf < 4; mf++)
#pragma unroll
                for (int nf = 0; nf < 8; nf++)
                    mma_f16(acc[mf][nf], areg[mf], breg[nf]);
        }

        if (has_next) {
#pragma unroll
            for (int i = 0; i < 4; i++) {
                *(uint4*)&sA[buf ^ 1][rg[i] * SSTRH + cg[i]] = qa[i];
                *(uint4*)&sB[buf ^ 1][rg[i] * SSTRH + cg[i]] = qb[i];
            }
            __syncthreads();
        }
    }

#pragma unroll
    for (int mf = 0; mf < 4; mf++) {
        int row = m0 + wm + mf * 16 + fr;
#pragma unroll
        for (int nf = 0; nf < 8; nf++) {
            int col = n0 + wn + nf * 8 + 2 * fc;
            float bx = bias[col], by = bias[col + 1];
            if (HALF_OUT) {
                __half* outh = (__half*)outv;
                *(unsigned*)(outh + (size_t)row * Nout + col) =
                    packh2(acc[mf][nf][0] + bx, acc[mf][nf][1] + by);
                *(unsigned*)(outh + (size_t)(row + 8) * Nout + col) =
                    packh2(acc[mf][nf][2] + bx, acc[mf][nf][3] + by);
            } else {
                float* outf = (float*)outv;
                *(float2*)(outf + (size_t)row * Nout + col) =
                    make_float2(acc[mf][nf][0] + bx, acc[mf][nf][1] + by);
                *(float2*)(outf + (size_t)(row + 8) * Nout + col) =
                    make_float2(acc[mf][nf][2] + bx, acc[mf][nf][3] + by);
            }
        }
    }
}

// ---------------------------------------------------------------------------
// RoPE2D + split qkv (f32 in/out), [b*H+h][n][d] layout.  (R11 version)
// ---------------------------------------------------------------------------
__global__ void rope_split_kernel(const int* __restrict__ pos2d)
{
    int idx = blockIdx.x * blockDim.x + threadIdx.x;
    const int total = B_ * N_ * H_ * DH_;
    if (idx >= total) return;

    int d = idx & 63;
    int h = (idx >> 6) % H_;
    int n = (idx / (H_ * DH_)) % N_;
    int b = idx / (N_ * H_ * DH_);

    const float* row = g_qkv + (size_t)(b * N_ + n) * (3 * C_);
    float qv = row[h * 64 + d];
    float kv = row[C_ + h * 64 + d];
    float vv = row[2 * C_ + h * 64 + d];

    if (n < NIMG_) {
        int half = d >> 5;
        int dl = d & 31;
        int f = dl & 15;
        int pos = pos2d[((size_t)b * NIMG_ + n) * 2 + half];
        float inv = exp2f(-0.41524101186f * (float)f);  // 100^(-f/16)
        float ang = (float)pos * inv;
        float s, c;
        sincosf(ang, &s, &c);
        int pd = (dl < 16) ? (d + 16) : (d - 16);
        float sign = (dl < 16) ? -1.0f : 1.0f;
        float qp = row[h * 64 + pd];
        float kp = row[C_ + h * 64 + pd];
        qv = qv * c + sign * qp * s;
        kv = kv * c + sign * kp * s;
    }

    size_t o = ((size_t)(b * H_ + h) * N_ + n) * DH_ + d;
    g_q[o] = qv; g_k[o] = kv; g_v[o] = vv;
}

// ---------------------------------------------------------------------------
// FP16 flash attention (R11 measured-good), fp16 OUTPUT for the proj GEMM.
// Grid: (N/64, B*H). 128 threads = 4 warps, warp w owns q-rows [16w,16w+16).
// ---------------------------------------------------------------------------
#define ASTRH 72
#define ATTN_SMEM_BYTES (4 * 64 * ASTRH * 2)

__global__ void __launch_bounds__(128) attn_mma_kernel(__half* __restrict__ out)
{
    extern __shared__ __align__(16) __half smh[];
    __half* sQ = smh;
    __half* sK = smh + 64 * ASTRH;
    __half* sVt = smh + 2 * 64 * ASTRH;
    __half* sP = smh + 3 * 64 * ASTRH;

    const int t = threadIdx.x;
    const int lane = t & 31;
    const int w = t >> 5;
    const int fr = lane >> 2;
    const int fc = lane & 3;
    const int wm = w * 16;
    const int bh = blockIdx.y;
    const int q0 = blockIdx.x * 64;

    const int lg = lane >> 3, lr = lane & 7;
    const int a_off = ((lg & 1) * 8 + lr) * ASTRH + (lg >> 1) * 8;
    const int b_off = ((lg >> 1) * 8 + lr) * ASTRH + (lg & 1) * 8;

    const float* Qg = g_q + ((size_t)bh * N_ + q0) * DH_;
    const float* Kg = g_k + (size_t)bh * N_ * DH_;
    const float* Vg = g_v + (size_t)bh * N_ * DH_;

#pragma unroll
    for (int i = 0; i < 8; i++) {
        int idx4 = t + i * 128;
        int r = idx4 >> 4;
        int c4 = (idx4 & 15) * 4;
        float4 v4 = *(const float4*)(Qg + (size_t)r * 64 + c4);
        *(uint2*)&sQ[r * ASTRH + c4] =
            make_uint2(packh2(v4.x, v4.y), packh2(v4.z, v4.w));
    }

    float m0 = -1e30f, m1 = -1e30f, l0 = 0.f, l1 = 0.f;
    float oacc[8][4];
#pragma unroll
    for (int nf = 0; nf < 8; nf++)
#pragma unroll
        for (int v = 0; v < 4; v++) oacc[nf][v] = 0.f;

    const int vd = 32 * (w & 1) + lane;
    const int vkb = (w >> 1) * 4;

    for (int kb = 0; kb < N_; kb += 64) {
        if (kb) __syncthreads();
#pragma unroll
        for (int i = 0; i < 8; i++) {
            int idx4 = t + i * 128;
            int r = idx4 >> 4;
            int c4 = (idx4 & 15) * 4;
            float4 k4 = *(const float4*)(Kg + (size_t)(kb + r) * 64 + c4);
            *(uint2*)&sK[r * ASTRH + c4] =
                make_uint2(packh2(k4.x, k4.y), packh2(k4.z, k4.w));
        }
#pragma unroll
        for (int i = 0; i < 8; i++) {
            int key0 = vkb + i * 8;
            float v0 = Vg[(size_t)(kb + key0 + 0) * 64 + vd];
            float v1 = Vg[(size_t)(kb + key0 + 1) * 64 + vd];
            float v2 = Vg[(size_t)(kb + key0 + 2) * 64 + vd];
            float v3 = Vg[(size_t)(kb + key0 + 3) * 64 + vd];
            *(uint2*)&sVt[vd * ASTRH + key0] =
                make_uint2(packh2(v0, v1), packh2(v2, v3));
        }
        __syncthreads();

        float sacc[8][4];
#pragma unroll
        for (int nf = 0; nf < 8; nf++)
#pragma unroll
            for (int v = 0; v < 4; v++) sacc[nf][v] = 0.f;
#pragma unroll
        for (int kc = 0; kc < 4; kc++) {
            unsigned a[4], breg[8][2];
            ldsm_x4(a[0], a[1], a[2], a[3], sptr(sQ + wm * ASTRH + kc * 16 + a_off));
#pragma unroll
            for (int np = 0; np < 4; np++)
                ldsm_x4(breg[np * 2][0], breg[np * 2][1],
                        breg[np * 2 + 1][0], breg[np * 2 + 1][1],
                        sptr(sK + np * 16 * ASTRH + kc * 16 + b_off));
#pragma unroll
            for (int nf = 0; nf < 8; nf++)
                mma_f16(sacc[nf], a, breg[nf]);
        }

        const float scale = 0.125f;
        float rm0 = -1e30f, rm1 = -1e30f;
#pragma unroll
        for (int nf = 0; nf < 8; nf++) {
#pragma unroll
            for (int v = 0; v < 4; v++) sacc[nf][v] *= scale;
            rm0 = fmaxf(rm0, fmaxf(sacc[nf][0], sacc[nf][1]));
            rm1 = fmaxf(rm1, fmaxf(sacc[nf][2], sacc[nf][3]));
        }
#pragma unroll
        for (int off = 1; off < 4; off <<= 1) {
            rm0 = fmaxf(rm0, __shfl_xor_sync(0xffffffffu, rm0, off));
            rm1 = fmaxf(rm1, __shfl_xor_sync(0xffffffffu, rm1, off));
        }
        float mn0 = fmaxf(m0, rm0), mn1 = fmaxf(m1, rm1);
        float corr0 = __expf(m0 - mn0), corr1 = __expf(m1 - mn1);
        m0 = mn0; m1 = mn1;
        float rs0 = 0.f, rs1 = 0.f;
#pragma unroll
        for (int nf = 0; nf < 8; nf++) {
            float p0 = __expf(sacc[nf][0] - mn0);
            float p1 = __expf(sacc[nf][1] - mn0);
            float p2 = __expf(sacc[nf][2] - mn1);
            float p3 = __expf(sacc[nf][3] - mn1);
            sacc[nf][0] = p0; sacc[nf][1] = p1; sacc[nf][2] = p2; sacc[nf][3] = p3;
            rs0 += p0 + p1; rs1 += p2 + p3;
        }
#pragma unroll
        for (int off = 1; off < 4; off <<= 1) {
            rs0 += __shfl_xor_sync(0xffffffffu, rs0, off);
            rs1 += __shfl_xor_sync(0xffffffffu, rs1, off);
        }
        l0 = l0 * corr0 + rs0;
        l1 = l1 * corr1 + rs1;
#pragma unroll
        for (int nf = 0; nf < 8; nf++) {
            oacc[nf][0] *= corr0; oacc[nf][1] *= corr0;
            oacc[nf][2] *= corr1; oacc[nf][3] *= corr1;
        }

#pragma unroll
        for (int nf = 0; nf < 8; nf++) {
            *(unsigned*)&sP[(wm + fr) * ASTRH + nf * 8 + 2 * fc] =
                packh2(sacc[nf][0], sacc[nf][1]);
            *(unsigned*)&sP[(wm + fr + 8) * ASTRH + nf * 8 + 2 * fc] =
                packh2(sacc[nf][2], sacc[nf][3]);
        }
        __syncwarp();

#pragma unroll
        for (int kc = 0; kc < 4; kc++) {
            unsigned a[4], breg[8][2];
            ldsm_x4(a[0], a[1], a[2], a[3], sptr(sP + wm * ASTRH + kc * 16 + a_off));
#pragma unroll
            for (int np = 0; np < 4; np++)
                ldsm_x4(breg[np * 2][0], breg[np * 2][1],
                        breg[np * 2 + 1][0], breg[np * 2 + 1][1],
                        sptr(sVt + np * 16 * ASTRH + kc * 16 + b_off));
#pragma unroll
            for (int nf = 0; nf < 8; nf++)
                mma_f16(oacc[nf], a, breg[nf]);
        }
    }

    const float inv0 = 1.0f / l0;
    const float inv1 = 1.0f / l1;
    const int b = bh / H_;
    const int h = bh % H_;
    const int r0 = q0 + wm + fr;
#pragma unroll
    for (int nf = 0; nf < 8; nf++) {
        int col = h * 64 + nf * 8 + 2 * fc;
        *(unsigned*)(out + (size_t)(b * N_ + r0) * C_ + col) =
            packh2(oacc[nf][0] * inv0, oacc[nf][1] * inv0);
        *(unsigned*)(out + (size_t)(b * N_ + r0 + 8) * C_ + col) =
            packh2(oacc[nf][2] * inv1, oacc[nf][3] * inv1);
    }
}

// ---------------------------------------------------------------------------
extern "C" void kernel_launch(void* const* d_in, const int* in_sizes, int n_in,
                              void* d_out, int out_size)
{
    const float* x_t    = (const float*)d_in[0];
    const float* qkv_w  = (const float*)d_in[1];
    const float* qkv_b  = (const float*)d_in[2];
    const float* proj_w = (const float*)d_in[3];
    const float* proj_b = (const float*)d_in[4];
    const int*   pos2d  = (const int*)d_in[5];
    float* out = (float*)d_out;

    float* p_qkv;
    __half *p_x, *p_qkvw, *p_projw, *p_aoh;
    cudaGetSymbolAddress((void**)&p_qkv, g_qkv);
    cudaGetSymbolAddress((void**)&p_x, gh_x);
    cudaGetSymbolAddress((void**)&p_qkvw, gh_qkvw);
    cudaGetSymbolAddress((void**)&p_projw, gh_projw);
    cudaGetSymbolAddress((void**)&p_aoh, g_aoh);

    cudaFuncSetAttribute(attn_mma_kernel,
                         cudaFuncAttributeMaxDynamicSharedMemorySize,
                         ATTN_SMEM_BYTES);

    // 0) one-time f32->f16 conversions of inputs
    {
        int nx = B_ * N_ * C_ / 8;
        f2h_kernel<<<(nx + 255) / 256, 256>>>(x_t, p_x, nx);
        int nw = 3 * C_ * C_ / 8;
        f2h_kernel<<<(nw + 255) / 256, 256>>>(qkv_w, p_qkvw, nw);
        int np = C_ * C_ / 8;
        f2h_kernel<<<(np + 255) / 256, 256>>>(proj_w, p_projw, np);
    }
    // 1) QKV GEMM (fp16 in, f32 out): [8192,768] x [2304,768]^T -> [8192,2304]
    {
        dim3 grid((3 * C_) / 128, (B_ * N_) / 128);
        gemm_h<false><<<grid, 128>>>(p_x, p_qkvw, qkv_b, p_qkv,
                                     B_ * N_, 3 * C_, C_);
    }
    // 2) RoPE2D + split (f32)
    {
        int total = B_ * N_ * H_ * DH_;
        rope_split_kernel<<<(total + 255) / 256, 256>>>(pos2d);
    }
    // 3) Attention (fp16 MMA, fp16 out)
    {
        dim3 grid(N_ / 64, B_ * H_);
        attn_mma_kernel<<<grid, 128, ATTN_SMEM_BYTES>>>(p_aoh);
    }
    // 4) Output projection (fp16 in, f32 out): [8192,768] x [768,768]^T
    {
        dim3 grid(C_ / 128, (B_ * N_) / 128);
        gemm_h<false><<<grid, 128>>>(p_aoh, p_projw, proj_b, out,
                                     B_ * N_, C_, C_);
    }
}

// round 14
// speedup vs baseline: 1.8069x; 1.8069x over previous
#include <cuda_runtime.h>
#include <cuda_fp16.h>
#include <cstdint>
#include <stdint.h>
#include <math.h>

#define B_ 8
#define N_ 1024
#define C_ 768
#define H_ 12
#define DH_ 64
#define NIMG_ 784

// Scratch (static device arrays: allocation-free per harness rules)
__device__ __half g_qh[B_ * H_ * N_ * DH_];     // [bh][n][d] fp16
__device__ __half g_kh[B_ * H_ * N_ * DH_];
__device__ __half g_vh[B_ * H_ * N_ * DH_];
__device__ float  g_ao[B_ * N_ * C_];           // attention out (f32)

__device__ __forceinline__ unsigned packh2(float a, float b) {
    __half2 h = __floats2half2_rn(a, b);
    return *(unsigned*)&h;
}

__device__ __forceinline__ void mma_f16(float* d, const unsigned* a, const unsigned* b) {
    asm volatile(
        "mma.sync.aligned.m16n8k16.row.col.f32.f16.f16.f32 "
        "{%0,%1,%2,%3}, {%4,%5,%6,%7}, {%8,%9}, {%0,%1,%2,%3};"
        : "+f"(d[0]), "+f"(d[1]), "+f"(d[2]), "+f"(d[3])
        : "r"(a[0]), "r"(a[1]), "r"(a[2]), "r"(a[3]), "r"(b[0]), "r"(b[1]));
}

__device__ __forceinline__ unsigned sptr(const void* p) {
    return (unsigned)__cvta_generic_to_shared(p);
}

__device__ __forceinline__ void ldsm_x4(unsigned& r0, unsigned& r1,
                                        unsigned& r2, unsigned& r3, unsigned addr) {
    asm volatile("ldmatrix.sync.aligned.m8n8.x4.shared.b16 {%0,%1,%2,%3}, [%4];"
        : "=r"(r0), "=r"(r1), "=r"(r2), "=r"(r3) : "r"(addr));
}

__device__ __forceinline__ void ldsm_x4_t(unsigned& r0, unsigned& r1,
                                          unsigned& r2, unsigned& r3, unsigned addr) {
    asm volatile("ldmatrix.sync.aligned.m8n8.x4.trans.shared.b16 {%0,%1,%2,%3}, [%4];"
        : "=r"(r0), "=r"(r1), "=r"(r2), "=r"(r3) : "r"(addr));
}

// ---------------------------------------------------------------------------
// FP16 tensor-core GEMM (fp32 accumulate), R11-measured-good geometry:
// block 128x128, BK=32, 256 threads = 8 warps (2m x 4n), warp tile 64x32,
// double-buffered smem, LDSM fragment loads. f32 inputs, cvt in loader.
// ROPE=false: f32 out + bias (proj).
// ROPE=true : QKV epilogue — bias, then RoPE2D on q/k thirds entirely in
//             registers (partner d^16 lives at nf^2 in the SAME thread),
//             writes q/k/v fp16 in [bh][n][d] layout.
// ---------------------------------------------------------------------------
#define BKh 32
#define SSTRH 40
#define SA_H (128 * SSTRH)

template <bool ROPE>
__global__ void __launch_bounds__(256, 2) gemm_k(
    const float* __restrict__ A, const float* __restrict__ W,
    const float* __restrict__ bias, float* __restrict__ outf,
    const int* __restrict__ pos2d, int M, int Nout, int K)
{
    __shared__ __align__(16) __half sA[2][SA_H];
    __shared__ __align__(16) __half sB[2][SA_H];

    const int t = threadIdx.x;
    const int lane = t & 31;
    const int warp = t >> 5;
    const int wm = (warp & 1) * 64;
    const int wn = (warp >> 1) * 32;
    const int m0 = blockIdx.y * 128;
    const int n0 = blockIdx.x * 128;

    // loader: 128 rows x 32 f32 cols per matrix = 1024 float4; 4 per thread
    int rg[4], cg[4];
#pragma unroll
    for (int i = 0; i < 4; i++) { rg[i] = (t + i * 256) >> 3; cg[i] = ((t + i * 256) & 7) * 4; }

    const int lg = lane >> 3, lr = lane & 7;
    const int a_off = ((lg & 1) * 8 + lr) * SSTRH + (lg >> 1) * 8;
    const int b_off = ((lg >> 1) * 8 + lr) * SSTRH + (lg & 1) * 8;

    float acc[4][4][4];
#pragma unroll
    for (int i = 0; i < 4; i++)
#pragma unroll
        for (int j = 0; j < 4; j++)
#pragma unroll
            for (int v = 0; v < 4; v++) acc[i][j][v] = 0.f;

    const int fr = lane >> 2;
    const int fc = lane & 3;

    float4 pa[4], pb[4];
#pragma unroll
    for (int i = 0; i < 4; i++) {
        pa[i] = *(const float4*)(A + (size_t)(m0 + rg[i]) * K + cg[i]);
        pb[i] = *(const float4*)(W + (size_t)(n0 + rg[i]) * K + cg[i]);
    }
#pragma unroll
    for (int i = 0; i < 4; i++) {
        *(uint2*)&sA[0][rg[i] * SSTRH + cg[i]] =
            make_uint2(packh2(pa[i].x, pa[i].y), packh2(pa[i].z, pa[i].w));
        *(uint2*)&sB[0][rg[i] * SSTRH + cg[i]] =
            make_uint2(packh2(pb[i].x, pb[i].y), packh2(pb[i].z, pb[i].w));
    }
    __syncthreads();

    const int nIter = K / BKh;
    for (int it = 0; it < nIter; it++) {
        const int buf = it & 1;
        const bool has_next = (it + 1) < nIter;

        if (has_next) {
            int kn = (it + 1) * BKh;
#pragma unroll
            for (int i = 0; i < 4; i++) {
                pa[i] = *(const float4*)(A + (size_t)(m0 + rg[i]) * K + kn + cg[i]);
                pb[i] = *(const float4*)(W + (size_t)(n0 + rg[i]) * K + kn + cg[i]);
            }
        }

        const __half* cA = sA[buf];
        const __half* cB = sB[buf];
#pragma unroll
        for (int ks = 0; ks < 2; ks++) {
            unsigned areg[4][4], breg[4][2];
#pragma unroll
            for (int mf = 0; mf < 4; mf++)
                ldsm_x4(areg[mf][0], areg[mf][1], areg[mf][2], areg[mf][3],
                        sptr(cA + (wm + mf * 16) * SSTRH + ks * 16 + a_off));
#pragma unroll
            for (int np = 0; np < 2; np++)
                ldsm_x4(breg[np * 2][0], breg[np * 2][1],
                        breg[np * 2 + 1][0], breg[np * 2 + 1][1],
                        sptr(cB + (wn + np * 16) * SSTRH + ks * 16 + b_off));
#pragma unroll
            for (int mf = 0; mf < 4; mf++)
#pragma unroll
                for (int nf = 0; nf < 4; nf++)
                    mma_f16(acc[mf][nf], areg[mf], breg[nf]);
        }

        if (has_next) {
#pragma unroll
            for (int i = 0; i < 4; i++) {
                *(uint2*)&sA[buf ^ 1][rg[i] * SSTRH + cg[i]] =
                    make_uint2(packh2(pa[i].x, pa[i].y), packh2(pa[i].z, pa[i].w));
                *(uint2*)&sB[buf ^ 1][rg[i] * SSTRH + cg[i]] =
                    make_uint2(packh2(pb[i].x, pb[i].y), packh2(pb[i].z, pb[i].w));
            }
            __syncthreads();
        }
    }

    if (!ROPE) {
#pragma unroll
        for (int mf = 0; mf < 4; mf++) {
            int row = m0 + wm + mf * 16 + fr;
#pragma unroll
            for (int nf = 0; nf < 4; nf++) {
                int col = n0 + wn + nf * 8 + 2 * fc;
                float bx = bias[col], by = bias[col + 1];
                *(float2*)(outf + (size_t)row * Nout + col) =
                    make_float2(acc[mf][nf][0] + bx, acc[mf][nf][1] + by);
                *(float2*)(outf + (size_t)(row + 8) * Nout + col) =
                    make_float2(acc[mf][nf][2] + bx, acc[mf][nf][3] + by);
            }
        }
    } else {
        // warp tile = one aligned 32-col block = one RoPE half of one head
        const int colbase = n0 + wn;
        const int third = colbase / C_;          // 0=q, 1=k, 2=v
        const int cw = colbase - third * C_;
        const int h = cw >> 6;
        const int half01 = (cw >> 5) & 1;        // 0=y-half, 1=x-half
        __half* dst = (third == 0) ? g_qh : (third == 1) ? g_kh : g_vh;

#pragma unroll
        for (int mf = 0; mf < 4; mf++) {
#pragma unroll
            for (int rh = 0; rh < 2; rh++) {
                int row = m0 + wm + mf * 16 + fr + rh * 8;
                int b = row >> 10, n = row & 1023;
                float v[4][2], o[4][2];
#pragma unroll
                for (int nf = 0; nf < 4; nf++) {
                    int col = colbase + nf * 8 + 2 * fc;
                    v[nf][0] = acc[mf][nf][rh * 2 + 0] + bias[col];
                    v[nf][1] = acc[mf][nf][rh * 2 + 1] + bias[col + 1];
                }
                if (third != 2 && n < NIMG_) {
                    int pos = pos2d[((size_t)b * NIMG_ + n) * 2 + half01];
#pragma unroll
                    for (int nf = 0; nf < 2; nf++) {
#pragma unroll
                        for (int j = 0; j < 2; j++) {
                            int f = nf * 8 + 2 * fc + j;   // 0..15
                            float inv = exp2f(-0.41524101186f * (float)f);
                            float s, c;
                            sincosf((float)pos * inv, &s, &c);
                            o[nf][j]     = v[nf][j] * c - v[nf + 2][j] * s;
                            o[nf + 2][j] = v[nf + 2][j] * c + v[nf][j] * s;
                        }
                    }
                } else {
#pragma unroll
                    for (int nf = 0; nf < 4; nf++) {
                        o[nf][0] = v[nf][0]; o[nf][1] = v[nf][1];
                    }
                }
                size_t base = ((size_t)(b * H_ + h) * N_ + n) * DH_ + half01 * 32;
#pragma unroll
                for (int nf = 0; nf < 4; nf++) {
                    int i = nf * 8 + 2 * fc;
                    *(unsigned*)(dst + base + i) = packh2(o[nf][0], o[nf][1]);
                }
            }
        }
    }
}

// ---------------------------------------------------------------------------
// FP16 flash attention (R11 mainloop), fp16 q/k/v inputs, ldmatrix.trans for V.
// Grid: (N/64, B*H). 128 threads = 4 warps, warp w owns q-rows [16w,16w+16).
// smem: sQ/sK/sV/sP each 64 rows x 72 halves.
// ---------------------------------------------------------------------------
#define ASTRH 72
#define ATTN_SMEM_BYTES (4 * 64 * ASTRH * 2)

__global__ void __launch_bounds__(128) attn_mma_kernel(float* __restrict__ out)
{
    extern __shared__ __align__(16) __half smh[];
    __half* sQ = smh;
    __half* sK = smh + 64 * ASTRH;
    __half* sV = smh + 2 * 64 * ASTRH;   // [key][d] row-major
    __half* sP = smh + 3 * 64 * ASTRH;

    const int t = threadIdx.x;
    const int lane = t & 31;
    const int w = t >> 5;
    const int fr = lane >> 2;
    const int fc = lane & 3;
    const int wm = w * 16;
    const int bh = blockIdx.y;
    const int q0 = blockIdx.x * 64;

    const int lg = lane >> 3, lr = lane & 7;
    const int a_off = ((lg & 1) * 8 + lr) * ASTRH + (lg >> 1) * 8;
    const int b_off = ((lg >> 1) * 8 + lr) * ASTRH + (lg & 1) * 8;

    const __half* Qg = g_qh + ((size_t)bh * N_ + q0) * DH_;
    const __half* Kg = g_kh + (size_t)bh * N_ * DH_;
    const __half* Vg = g_vh + (size_t)bh * N_ * DH_;

    // Q tile 64x64 halves = 512 uint4, 4 per thread
#pragma unroll
    for (int i = 0; i < 4; i++) {
        int idx8 = t + i * 128;
        int r = idx8 >> 3;
        int c8 = (idx8 & 7) * 8;
        *(uint4*)&sQ[r * ASTRH + c8] = *(const uint4*)(Qg + (size_t)r * 64 + c8);
    }

    float m0 = -1e30f, m1 = -1e30f, l0 = 0.f, l1 = 0.f;
    float oacc[8][4];
#pragma unroll
    for (int nf = 0; nf < 8; nf++)
#pragma unroll
        for (int v = 0; v < 4; v++) oacc[nf][v] = 0.f;

    for (int kb = 0; kb < N_; kb += 64) {
        if (kb) __syncthreads();
#pragma unroll
        for (int i = 0; i < 4; i++) {
            int idx8 = t + i * 128;
            int r = idx8 >> 3;
            int c8 = (idx8 & 7) * 8;
            *(uint4*)&sK[r * ASTRH + c8] = *(const uint4*)(Kg + (size_t)(kb + r) * 64 + c8);
            *(uint4*)&sV[r * ASTRH + c8] = *(const uint4*)(Vg + (size_t)(kb + r) * 64 + c8);
        }
        __syncthreads();

        // S = Q K^T : 4 k16 steps
        float sacc[8][4];
#pragma unroll
        for (int nf = 0; nf < 8; nf++)
#pragma unroll
            for (int v = 0; v < 4; v++) sacc[nf][v] = 0.f;
#pragma unroll
        for (int kc = 0; kc < 4; kc++) {
            unsigned a[4], breg[8][2];
            ldsm_x4(a[0], a[1], a[2], a[3], sptr(sQ + wm * ASTRH + kc * 16 + a_off));
#pragma unroll
            for (int np = 0; np < 4; np++)
                ldsm_x4(breg[np * 2][0], breg[np * 2][1],
                        breg[np * 2 + 1][0], breg[np * 2 + 1][1],
                        sptr(sK + np * 16 * ASTRH + kc * 16 + b_off));
#pragma unroll
            for (int nf = 0; nf < 8; nf++)
                mma_f16(sacc[nf], a, breg[nf]);
        }

        const float scale = 0.125f;
        float rm0 = -1e30f, rm1 = -1e30f;
#pragma unroll
        for (int nf = 0; nf < 8; nf++) {
#pragma unroll
            for (int v = 0; v < 4; v++) sacc[nf][v] *= scale;
            rm0 = fmaxf(rm0, fmaxf(sacc[nf][0], sacc[nf][1]));
            rm1 = fmaxf(rm1, fmaxf(sacc[nf][2], sacc[nf][3]));
        }
#pragma unroll
        for (int off = 1; off < 4; off <<= 1) {
            rm0 = fmaxf(rm0, __shfl_xor_sync(0xffffffffu, rm0, off));
            rm1 = fmaxf(rm1, __shfl_xor_sync(0xffffffffu, rm1, off));
        }
        float mn0 = fmaxf(m0, rm0), mn1 = fmaxf(m1, rm1);
        float corr0 = __expf(m0 - mn0), corr1 = __expf(m1 - mn1);
        m0 = mn0; m1 = mn1;
        float rs0 = 0.f, rs1 = 0.f;
#pragma unroll
        for (int nf = 0; nf < 8; nf++) {
            float p0 = __expf(sacc[nf][0] - mn0);
            float p1 = __expf(sacc[nf][1] - mn0);
            float p2 = __expf(sacc[nf][2] - mn1);
            float p3 = __expf(sacc[nf][3] - mn1);
            sacc[nf][0] = p0; sacc[nf][1] = p1; sacc[nf][2] = p2; sacc[nf][3] = p3;
            rs0 += p0 + p1; rs1 += p2 + p3;
        }
#pragma unroll
        for (int off = 1; off < 4; off <<= 1) {
            rs0 += __shfl_xor_sync(0xffffffffu, rs0, off);
            rs1 += __shfl_xor_sync(0xffffffffu, rs1, off);
        }
        l0 = l0 * corr0 + rs0;
        l1 = l1 * corr1 + rs1;
#pragma unroll
        for (int nf = 0; nf < 8; nf++) {
            oacc[nf][0] *= corr0; oacc[nf][1] *= corr0;
            oacc[nf][2] *= corr1; oacc[nf][3] *= corr1;
        }

        // P -> sP as fp16 (warp-private rows)
#pragma unroll
        for (int nf = 0; nf < 8; nf++) {
            *(unsigned*)&sP[(wm + fr) * ASTRH + nf * 8 + 2 * fc] =
                packh2(sacc[nf][0], sacc[nf][1]);
            *(unsigned*)&sP[(wm + fr + 8) * ASTRH + nf * 8 + 2 * fc] =
                packh2(sacc[nf][2], sacc[nf][3]);
        }
        __syncwarp();

        // O += P V : B-fragments via ldmatrix.trans on row-major sV[key][d]
#pragma unroll
        for (int kc = 0; kc < 4; kc++) {
            unsigned a[4], breg[8][2];
            ldsm_x4(a[0], a[1], a[2], a[3], sptr(sP + wm * ASTRH + kc * 16 + a_off));
#pragma unroll
            for (int np = 0; np < 4; np++)
                ldsm_x4_t(breg[np * 2][0], breg[np * 2][1],
                          breg[np * 2 + 1][0], breg[np * 2 + 1][1],
                          sptr(sV + kc * 16 * ASTRH + np * 16 + a_off));
#pragma unroll
            for (int nf = 0; nf < 8; nf++)
                mma_f16(oacc[nf], a, breg[nf]);
        }
    }

    const float inv0 = 1.0f / l0;
    const float inv1 = 1.0f / l1;
    const int b = bh / H_;
    const int h = bh % H_;
    const int r0 = q0 + wm + fr;
#pragma unroll
    for (int nf = 0; nf < 8; nf++) {
        int col = h * 64 + nf * 8 + 2 * fc;
        *(float2*)(out + (size_t)(b * N_ + r0) * C_ + col) =
            make_float2(oacc[nf][0] * inv0, oacc[nf][1] * inv0);
        *(float2*)(out + (size_t)(b * N_ + r0 + 8) * C_ + col) =
            make_float2(oacc[nf][2] * inv1, oacc[nf][3] * inv1);
    }
}

// ---------------------------------------------------------------------------
extern "C" void kernel_launch(void* const* d_in, const int* in_sizes, int n_in,
                              void* d_out, int out_size)
{
    const float* x_t    = (const float*)d_in[0];
    const float* qkv_w  = (const float*)d_in[1];
    const float* qkv_b  = (const float*)d_in[2];
    const float* proj_w = (const float*)d_in[3];
    const float* proj_b = (const float*)d_in[4];
    const int*   pos2d  = (const int*)d_in[5];
    float* out = (float*)d_out;

    float* p_ao;
    cudaGetSymbolAddress((void**)&p_ao, g_ao);

    cudaFuncSetAttribute(attn_mma_kernel,
                         cudaFuncAttributeMaxDynamicSharedMemorySize,
                         ATTN_SMEM_BYTES);

    // 1) QKV GEMM + fused bias + RoPE2D + split -> fp16 q/k/v
    {
        dim3 grid((3 * C_) / 128, (B_ * N_) / 128);
        gemm_k<true><<<grid, 256>>>(x_t, qkv_w, qkv_b, nullptr, pos2d,
                                    B_ * N_, 3 * C_, C_);
    }
    // 2) Attention (fp16 MMA + LDSM/LDSM.T) -> f32 g_ao
    {
        dim3 grid(N_ / 64, B_ * H_);
        attn_mma_kernel<<<grid, 128, ATTN_SMEM_BYTES>>>(p_ao);
    }
    // 3) Output projection: [8192,768] x [768,768]^T -> [8192,768]
    {
        dim3 grid(C_ / 128, (B_ * N_) / 128);
        gemm_k<false><<<grid, 256>>>(p_ao, proj_w, proj_b, out, nullptr,
                                     B_ * N_, C_, C_);
    }
}

// round 15
// speedup vs baseline: 1.8254x; 1.0103x over previous
#include <cuda_runtime.h>
#include <cuda_fp16.h>
#include <cstdint>
#include <stdint.h>
#include <math.h>

#define B_ 8
#define N_ 1024
#define C_ 768
#define H_ 12
#define DH_ 64
#define NIMG_ 784
#define POSMAX 28

// Scratch (static device arrays: allocation-free per harness rules)
__device__ __half gh_x[B_ * N_ * C_];           // x_t fp16
__device__ __half gh_qkvw[3 * C_ * C_];         // qkv_w fp16
__device__ __half gh_projw[C_ * C_];            // proj_w fp16
__device__ __half g_qh[B_ * H_ * N_ * DH_];     // [bh][n][d] fp16
__device__ __half g_kh[B_ * H_ * N_ * DH_];
__device__ __half g_vh[B_ * H_ * N_ * DH_];
__device__ __half g_aoh[B_ * N_ * C_];          // attention out fp16
__device__ float2 g_rope_tab[POSMAX * 16];      // (cos, sin) per (pos, f)

__device__ __forceinline__ unsigned packh2(float a, float b) {
    __half2 h = __floats2half2_rn(a, b);
    return *(unsigned*)&h;
}

__device__ __forceinline__ void mma_f16(float* d, const unsigned* a, const unsigned* b) {
    asm volatile(
        "mma.sync.aligned.m16n8k16.row.col.f32.f16.f16.f32 "
        "{%0,%1,%2,%3}, {%4,%5,%6,%7}, {%8,%9}, {%0,%1,%2,%3};"
        : "+f"(d[0]), "+f"(d[1]), "+f"(d[2]), "+f"(d[3])
        : "r"(a[0]), "r"(a[1]), "r"(a[2]), "r"(a[3]), "r"(b[0]), "r"(b[1]));
}

__device__ __forceinline__ unsigned sptr(const void* p) {
    return (unsigned)__cvta_generic_to_shared(p);
}

__device__ __forceinline__ void ldsm_x4(unsigned& r0, unsigned& r1,
                                        unsigned& r2, unsigned& r3, unsigned addr) {
    asm volatile("ldmatrix.sync.aligned.m8n8.x4.shared.b16 {%0,%1,%2,%3}, [%4];"
        : "=r"(r0), "=r"(r1), "=r"(r2), "=r"(r3) : "r"(addr));
}

__device__ __forceinline__ void ldsm_x4_t(unsigned& r0, unsigned& r1,
                                          unsigned& r2, unsigned& r3, unsigned addr) {
    asm volatile("ldmatrix.sync.aligned.m8n8.x4.trans.shared.b16 {%0,%1,%2,%3}, [%4];"
        : "=r"(r0), "=r"(r1), "=r"(r2), "=r"(r3) : "r"(addr));
}

// ---------------------------------------------------------------------------
// Setup kernels: f32->f16 convert; RoPE sincos table
// ---------------------------------------------------------------------------
__global__ void f2h_kernel(const float* __restrict__ in, __half* __restrict__ out, int n8)
{
    int i = blockIdx.x * blockDim.x + threadIdx.x;
    if (i >= n8) return;
    float4 a = ((const float4*)in)[i * 2];
    float4 b = ((const float4*)in)[i * 2 + 1];
    uint4 u;
    u.x = packh2(a.x, a.y); u.y = packh2(a.z, a.w);
    u.z = packh2(b.x, b.y); u.w = packh2(b.z, b.w);
    ((uint4*)out)[i] = u;
}

__global__ void rope_tab_kernel()
{
    int i = blockIdx.x * blockDim.x + threadIdx.x;
    if (i >= POSMAX * 16) return;
    int pos = i >> 4, f = i & 15;
    float inv = exp2f(-0.41524101186f * (float)f);  // 100^(-f/16)
    float s, c;
    sincosf((float)pos * inv, &s, &c);
    g_rope_tab[i] = make_float2(c, s);
}

// ---------------------------------------------------------------------------
// FP16-input tensor-core GEMM (fp32 accumulate), R11/R14-measured geometry:
// block 128x128, BK=32, 256 threads = 8 warps (2m x 4n), warp tile 64x32,
// double-buffered smem (uint2 STS pattern identical to measured-good R11/R14).
// ROPE=false: f32 out + bias (proj).
// ROPE=true : QKV epilogue — bias + table-driven RoPE2D in registers,
//             writes q/k/v fp16 in [bh][n][d] layout.
// ---------------------------------------------------------------------------
#define BKh 32
#define SSTRH 40
#define SA_H (128 * SSTRH)

template <bool ROPE>
__global__ void __launch_bounds__(256, 2) gemm_k(
    const __half* __restrict__ A, const __half* __restrict__ W,
    const float* __restrict__ bias, float* __restrict__ outf,
    const int* __restrict__ pos2d, int M, int Nout, int K)
{
    __shared__ __align__(16) __half sA[2][SA_H];
    __shared__ __align__(16) __half sB[2][SA_H];

    const int t = threadIdx.x;
    const int lane = t & 31;
    const int warp = t >> 5;
    const int wm = (warp & 1) * 64;
    const int wn = (warp >> 1) * 32;
    const int m0 = blockIdx.y * 128;
    const int n0 = blockIdx.x * 128;

    // loader: 128 rows x 32 halves per matrix = 1024 uint2; 4 per thread
    int rg[4], cg[4];
#pragma unroll
    for (int i = 0; i < 4; i++) { rg[i] = (t + i * 256) >> 3; cg[i] = ((t + i * 256) & 7) * 4; }

    const int lg = lane >> 3, lr = lane & 7;
    const int a_off = ((lg & 1) * 8 + lr) * SSTRH + (lg >> 1) * 8;
    const int b_off = ((lg >> 1) * 8 + lr) * SSTRH + (lg & 1) * 8;

    float acc[4][4][4];
#pragma unroll
    for (int i = 0; i < 4; i++)
#pragma unroll
        for (int j = 0; j < 4; j++)
#pragma unroll
            for (int v = 0; v < 4; v++) acc[i][j][v] = 0.f;

    const int fr = lane >> 2;
    const int fc = lane & 3;

    uint2 qa[4], qb[4];
#pragma unroll
    for (int i = 0; i < 4; i++) {
        qa[i] = *(const uint2*)(A + (size_t)(m0 + rg[i]) * K + cg[i]);
        qb[i] = *(const uint2*)(W + (size_t)(n0 + rg[i]) * K + cg[i]);
    }
#pragma unroll
    for (int i = 0; i < 4; i++) {
        *(uint2*)&sA[0][rg[i] * SSTRH + cg[i]] = qa[i];
        *(uint2*)&sB[0][rg[i] * SSTRH + cg[i]] = qb[i];
    }
    __syncthreads();

    const int nIter = K / BKh;
    for (int it = 0; it < nIter; it++) {
        const int buf = it & 1;
        const bool has_next = (it + 1) < nIter;

        if (has_next) {
            int kn = (it + 1) * BKh;
#pragma unroll
            for (int i = 0; i < 4; i++) {
                qa[i] = *(const uint2*)(A + (size_t)(m0 + rg[i]) * K + kn + cg[i]);
                qb[i] = *(const uint2*)(W + (size_t)(n0 + rg[i]) * K + kn + cg[i]);
            }
        }

        const __half* cA = sA[buf];
        const __half* cB = sB[buf];
#pragma unroll
        for (int ks = 0; ks < 2; ks++) {
            unsigned areg[4][4], breg[4][2];
#pragma unroll
            for (int mf = 0; mf < 4; mf++)
                ldsm_x4(areg[mf][0], areg[mf][1], areg[mf][2], areg[mf][3],
                        sptr(cA + (wm + mf * 16) * SSTRH + ks * 16 + a_off));
#pragma unroll
            for (int np = 0; np < 2; np++)
                ldsm_x4(breg[np * 2][0], breg[np * 2][1],
                        breg[np * 2 + 1][0], breg[np * 2 + 1][1],
                        sptr(cB + (wn + np * 16) * SSTRH + ks * 16 + b_off));
#pragma unroll
            for (int mf = 0; mf < 4; mf++)
#pragma unroll
                for (int nf = 0; nf < 4; nf++)
                    mma_f16(acc[mf][nf], areg[mf], breg[nf]);
        }

        if (has_next) {
#pragma unroll
            for (int i = 0; i < 4; i++) {
                *(uint2*)&sA[buf ^ 1][rg[i] * SSTRH + cg[i]] = qa[i];
                *(uint2*)&sB[buf ^ 1][rg[i] * SSTRH + cg[i]] = qb[i];
            }
            __syncthreads();
        }
    }

    if (!ROPE) {
#pragma unroll
        for (int mf = 0; mf < 4; mf++) {
            int row = m0 + wm + mf * 16 + fr;
#pragma unroll
            for (int nf = 0; nf < 4; nf++) {
                int col = n0 + wn + nf * 8 + 2 * fc;
                float bx = bias[col], by = bias[col + 1];
                *(float2*)(outf + (size_t)row * Nout + col) =
                    make_float2(acc[mf][nf][0] + bx, acc[mf][nf][1] + by);
                *(float2*)(outf + (size_t)(row + 8) * Nout + col) =
                    make_float2(acc[mf][nf][2] + bx, acc[mf][nf][3] + by);
            }
        }
    } else {
        // warp tile = one aligned 32-col block = one RoPE half of one head
        const int colbase = n0 + wn;
        const int third = colbase / C_;          // 0=q, 1=k, 2=v
        const int cw = colbase - third * C_;
        const int h = cw >> 6;
        const int half01 = (cw >> 5) & 1;        // 0=y-half, 1=x-half
        __half* dst = (third == 0) ? g_qh : (third == 1) ? g_kh : g_vh;

#pragma unroll
        for (int mf = 0; mf < 4; mf++) {
#pragma unroll
            for (int rh = 0; rh < 2; rh++) {
                int row = m0 + wm + mf * 16 + fr + rh * 8;
                int b = row >> 10, n = row & 1023;
                float v[4][2], o[4][2];
#pragma unroll
                for (int nf = 0; nf < 4; nf++) {
                    int col = colbase + nf * 8 + 2 * fc;
                    v[nf][0] = acc[mf][nf][rh * 2 + 0] + bias[col];
                    v[nf][1] = acc[mf][nf][rh * 2 + 1] + bias[col + 1];
                }
                if (third != 2 && n < NIMG_) {
                    int pos = pos2d[((size_t)b * NIMG_ + n) * 2 + half01];
                    const float2* tab = g_rope_tab + pos * 16;
#pragma unroll
                    for (int nf = 0; nf < 2; nf++) {
#pragma unroll
                        for (int j = 0; j < 2; j++) {
                            int f = nf * 8 + 2 * fc + j;   // 0..15
                            float2 cs = tab[f];
                            o[nf][j]     = v[nf][j] * cs.x - v[nf + 2][j] * cs.y;
                            o[nf + 2][j] = v[nf + 2][j] * cs.x + v[nf][j] * cs.y;
                        }
                    }
                } else {
#pragma unroll
                    for (int nf = 0; nf < 4; nf++) {
                        o[nf][0] = v[nf][0]; o[nf][1] = v[nf][1];
                    }
                }
                size_t base = ((size_t)(b * H_ + h) * N_ + n) * DH_ + half01 * 32;
#pragma unroll
                for (int nf = 0; nf < 4; nf++) {
                    int i = nf * 8 + 2 * fc;
                    *(unsigned*)(dst + base + i) = packh2(o[nf][0], o[nf][1]);
                }
            }
        }
    }
}

// ---------------------------------------------------------------------------
// FP16 flash attention (R14 measured-good), fp16 output for the proj GEMM.
// Grid: (N/64, B*H). 128 threads = 4 warps, warp w owns q-rows [16w,16w+16).
// ---------------------------------------------------------------------------
#define ASTRH 72
#define ATTN_SMEM_BYTES (4 * 64 * ASTRH * 2)

__global__ void __launch_bounds__(128) attn_mma_kernel(__half* __restrict__ out)
{
    extern __shared__ __align__(16) __half smh[];
    __half* sQ = smh;
    __half* sK = smh + 64 * ASTRH;
    __half* sV = smh + 2 * 64 * ASTRH;   // [key][d] row-major
    __half* sP = smh + 3 * 64 * ASTRH;

    const int t = threadIdx.x;
    const int lane = t & 31;
    const int w = t >> 5;
    const int fr = lane >> 2;
    const int fc = lane & 3;
    const int wm = w * 16;
    const int bh = blockIdx.y;
    const int q0 = blockIdx.x * 64;

    const int lg = lane >> 3, lr = lane & 7;
    const int a_off = ((lg & 1) * 8 + lr) * ASTRH + (lg >> 1) * 8;
    const int b_off = ((lg >> 1) * 8 + lr) * ASTRH + (lg & 1) * 8;

    const __half* Qg = g_qh + ((size_t)bh * N_ + q0) * DH_;
    const __half* Kg = g_kh + (size_t)bh * N_ * DH_;
    const __half* Vg = g_vh + (size_t)bh * N_ * DH_;

    // Q tile 64x64 halves = 512 uint4, 4 per thread
#pragma unroll
    for (int i = 0; i < 4; i++) {
        int idx8 = t + i * 128;
        int r = idx8 >> 3;
        int c8 = (idx8 & 7) * 8;
        *(uint4*)&sQ[r * ASTRH + c8] = *(const uint4*)(Qg + (size_t)r * 64 + c8);
    }

    float m0 = -1e30f, m1 = -1e30f, l0 = 0.f, l1 = 0.f;
    float oacc[8][4];
#pragma unroll
    for (int nf = 0; nf < 8; nf++)
#pragma unroll
        for (int v = 0; v < 4; v++) oacc[nf][v] = 0.f;

    for (int kb = 0; kb < N_; kb += 64) {
        if (kb) __syncthreads();
#pragma unroll
        for (int i = 0; i < 4; i++) {
            int idx8 = t + i * 128;
            int r = idx8 >> 3;
            int c8 = (idx8 & 7) * 8;
            *(uint4*)&sK[r * ASTRH + c8] = *(const uint4*)(Kg + (size_t)(kb + r) * 64 + c8);
            *(uint4*)&sV[r * ASTRH + c8] = *(const uint4*)(Vg + (size_t)(kb + r) * 64 + c8);
        }
        __syncthreads();

        // S = Q K^T : 4 k16 steps
        float sacc[8][4];
#pragma unroll
        for (int nf = 0; nf < 8; nf++)
#pragma unroll
            for (int v = 0; v < 4; v++) sacc[nf][v] = 0.f;
#pragma unroll
        for (int kc = 0; kc < 4; kc++) {
            unsigned a[4], breg[8][2];
            ldsm_x4(a[0], a[1], a[2], a[3], sptr(sQ + wm * ASTRH + kc * 16 + a_off));
#pragma unroll
            for (int np = 0; np < 4; np++)
                ldsm_x4(breg[np * 2][0], breg[np * 2][1],
                        breg[np * 2 + 1][0], breg[np * 2 + 1][1],
                        sptr(sK + np * 16 * ASTRH + kc * 16 + b_off));
#pragma unroll
            for (int nf = 0; nf < 8; nf++)
                mma_f16(sacc[nf], a, breg[nf]);
        }

        const float scale = 0.125f;
        float rm0 = -1e30f, rm1 = -1e30f;
#pragma unroll
        for (int nf = 0; nf < 8; nf++) {
#pragma unroll
            for (int v = 0; v < 4; v++) sacc[nf][v] *= scale;
            rm0 = fmaxf(rm0, fmaxf(sacc[nf][0], sacc[nf][1]));
            rm1 = fmaxf(rm1, fmaxf(sacc[nf][2], sacc[nf][3]));
        }
#pragma unroll
        for (int off = 1; off < 4; off <<= 1) {
            rm0 = fmaxf(rm0, __shfl_xor_sync(0xffffffffu, rm0, off));
            rm1 = fmaxf(rm1, __shfl_xor_sync(0xffffffffu, rm1, off));
        }
        float mn0 = fmaxf(m0, rm0), mn1 = fmaxf(m1, rm1);
        float corr0 = __expf(m0 - mn0), corr1 = __expf(m1 - mn1);
        m0 = mn0; m1 = mn1;
        float rs0 = 0.f, rs1 = 0.f;
#pragma unroll
        for (int nf = 0; nf < 8; nf++) {
            float p0 = __expf(sacc[nf][0] - mn0);
            float p1 = __expf(sacc[nf][1] - mn0);
            float p2 = __expf(sacc[nf][2] - mn1);
            float p3 = __expf(sacc[nf][3] - mn1);
            sacc[nf][0] = p0; sacc[nf][1] = p1; sacc[nf][2] = p2; sacc[nf][3] = p3;
            rs0 += p0 + p1; rs1 += p2 + p3;
        }
#pragma unroll
        for (int off = 1; off < 4; off <<= 1) {
            rs0 += __shfl_xor_sync(0xffffffffu, rs0, off);
            rs1 += __shfl_xor_sync(0xffffffffu, rs1, off);
        }
        l0 = l0 * corr0 + rs0;
        l1 = l1 * corr1 + rs1;
#pragma unroll
        for (int nf = 0; nf < 8; nf++) {
            oacc[nf][0] *= corr0; oacc[nf][1] *= corr0;
            oacc[nf][2] *= corr1; oacc[nf][3] *= corr1;
        }

        // P -> sP as fp16 (warp-private rows)
#pragma unroll
        for (int nf = 0; nf < 8; nf++) {
            *(unsigned*)&sP[(wm + fr) * ASTRH + nf * 8 + 2 * fc] =
                packh2(sacc[nf][0], sacc[nf][1]);
            *(unsigned*)&sP[(wm + fr + 8) * ASTRH + nf * 8 + 2 * fc] =
                packh2(sacc[nf][2], sacc[nf][3]);
        }
        __syncwarp();

        // O += P V : B-fragments via ldmatrix.trans on row-major sV[key][d]
#pragma unroll
        for (int kc = 0; kc < 4; kc++) {
            unsigned a[4], breg[8][2];
            ldsm_x4(a[0], a[1], a[2], a[3], sptr(sP + wm * ASTRH + kc * 16 + a_off));
#pragma unroll
            for (int np = 0; np < 4; np++)
                ldsm_x4_t(breg[np * 2][0], breg[np * 2][1],
                          breg[np * 2 + 1][0], breg[np * 2 + 1][1],
                          sptr(sV + kc * 16 * ASTRH + np * 16 + a_off));
#pragma unroll
            for (int nf = 0; nf < 8; nf++)
                mma_f16(oacc[nf], a, breg[nf]);
        }
    }

    const float inv0 = 1.0f / l0;
    const float inv1 = 1.0f / l1;
    const int b = bh / H_;
    const int h = bh % H_;
    const int r0 = q0 + wm + fr;
#pragma unroll
    for (int nf = 0; nf < 8; nf++) {
        int col = h * 64 + nf * 8 + 2 * fc;
        *(unsigned*)(out + (size_t)(b * N_ + r0) * C_ + col) =
            packh2(oacc[nf][0] * inv0, oacc[nf][1] * inv0);
        *(unsigned*)(out + (size_t)(b * N_ + r0 + 8) * C_ + col) =
            packh2(oacc[nf][2] * inv1, oacc[nf][3] * inv1);
    }
}

// ---------------------------------------------------------------------------
extern "C" void kernel_launch(void* const* d_in, const int* in_sizes, int n_in,
                              void* d_out, int out_size)
{
    const float* x_t    = (const float*)d_in[0];
    const float* qkv_w  = (const float*)d_in[1];
    const float* qkv_b  = (const float*)d_in[2];
    const float* proj_w = (const float*)d_in[3];
    const float* proj_b = (const float*)d_in[4];
    const int*   pos2d  = (const int*)d_in[5];
    float* out = (float*)d_out;

    __half *p_x, *p_qkvw, *p_projw, *p_aoh;
    cudaGetSymbolAddress((void**)&p_x, gh_x);
    cudaGetSymbolAddress((void**)&p_qkvw, gh_qkvw);
    cudaGetSymbolAddress((void**)&p_projw, gh_projw);
    cudaGetSymbolAddress((void**)&p_aoh, g_aoh);

    cudaFuncSetAttribute(attn_mma_kernel,
                         cudaFuncAttributeMaxDynamicSharedMemorySize,
                         ATTN_SMEM_BYTES);

    // 0) setup: f32->f16 inputs + RoPE sincos table
    {
        int nx = B_ * N_ * C_ / 8;
        f2h_kernel<<<(nx + 255) / 256, 256>>>(x_t, p_x, nx);
        int nw = 3 * C_ * C_ / 8;
        f2h_kernel<<<(nw + 255) / 256, 256>>>(qkv_w, p_qkvw, nw);
        int np = C_ * C_ / 8;
        f2h_kernel<<<(np + 255) / 256, 256>>>(proj_w, p_projw, np);
        rope_tab_kernel<<<2, 256>>>();
    }
    // 1) QKV GEMM + fused bias + RoPE2D(table) + split -> fp16 q/k/v
    {
        dim3 grid((3 * C_) / 128, (B_ * N_) / 128);
        gemm_k<true><<<grid, 256>>>(p_x, p_qkvw, qkv_b, nullptr, pos2d,
                                    B_ * N_, 3 * C_, C_);
    }
    // 2) Attention (fp16 MMA + LDSM/LDSM.T) -> fp16 g_aoh
    {
        dim3 grid(N_ / 64, B_ * H_);
        attn_mma_kernel<<<grid, 128, ATTN_SMEM_BYTES>>>(p_aoh);
    }
    // 3) Output projection (fp16 in, f32 out): [8192,768] x [768,768]^T
    {
        dim3 grid(C_ / 128, (B_ * N_) / 128);
        gemm_k<false><<<grid, 256>>>(p_aoh, p_projw, proj_b, out, nullptr,
                                     B_ * N_, C_, C_);
    }
}

// round 16
// speedup vs baseline: 1.8266x; 1.0006x over previous
#include <cuda_runtime.h>
#include <cuda_fp16.h>
#include <cstdint>
#include <stdint.h>
#include <math.h>

#define B_ 8
#define N_ 1024
#define C_ 768
#define H_ 12
#define DH_ 64
#define NIMG_ 784
#define POSMAX 28

// Scratch (static device arrays: allocation-free per harness rules)
__device__ __half gh_x[B_ * N_ * C_];           // x_t fp16
__device__ __half gh_qkvw[3 * C_ * C_];         // qkv_w fp16
__device__ __half gh_projw[C_ * C_];            // proj_w fp16
__device__ __half g_qh[B_ * H_ * N_ * DH_];     // [bh][n][d] fp16
__device__ __half g_kh[B_ * H_ * N_ * DH_];
__device__ __half g_vh[B_ * H_ * N_ * DH_];
__device__ __half g_aoh[B_ * N_ * C_];          // attention out fp16
__device__ float2 g_rope_tab[POSMAX * 16];      // (cos, sin) per (pos, f)

__device__ __forceinline__ unsigned packh2(float a, float b) {
    __half2 h = __floats2half2_rn(a, b);
    return *(unsigned*)&h;
}

__device__ __forceinline__ void mma_f16(float* d, const unsigned* a, const unsigned* b) {
    asm volatile(
        "mma.sync.aligned.m16n8k16.row.col.f32.f16.f16.f32 "
        "{%0,%1,%2,%3}, {%4,%5,%6,%7}, {%8,%9}, {%0,%1,%2,%3};"
        : "+f"(d[0]), "+f"(d[1]), "+f"(d[2]), "+f"(d[3])
        : "r"(a[0]), "r"(a[1]), "r"(a[2]), "r"(a[3]), "r"(b[0]), "r"(b[1]));
}

__device__ __forceinline__ unsigned sptr(const void* p) {
    return (unsigned)__cvta_generic_to_shared(p);
}

__device__ __forceinline__ void ldsm_x4(unsigned& r0, unsigned& r1,
                                        unsigned& r2, unsigned& r3, unsigned addr) {
    asm volatile("ldmatrix.sync.aligned.m8n8.x4.shared.b16 {%0,%1,%2,%3}, [%4];"
        : "=r"(r0), "=r"(r1), "=r"(r2), "=r"(r3) : "r"(addr));
}

__device__ __forceinline__ void ldsm_x4_t(unsigned& r0, unsigned& r1,
                                          unsigned& r2, unsigned& r3, unsigned addr) {
    asm volatile("ldmatrix.sync.aligned.m8n8.x4.trans.shared.b16 {%0,%1,%2,%3}, [%4];"
        : "=r"(r0), "=r"(r1), "=r"(r2), "=r"(r3) : "r"(addr));
}

// ---------------------------------------------------------------------------
// Setup kernels: f32->f16 convert; RoPE sincos table
// ---------------------------------------------------------------------------
__global__ void f2h_kernel(const float* __restrict__ in, __half* __restrict__ out, int n8)
{
    int i = blockIdx.x * blockDim.x + threadIdx.x;
    if (i >= n8) return;
    float4 a = ((const float4*)in)[i * 2];
    float4 b = ((const float4*)in)[i * 2 + 1];
    uint4 u;
    u.x = packh2(a.x, a.y); u.y = packh2(a.z, a.w);
    u.z = packh2(b.x, b.y); u.w = packh2(b.z, b.w);
    ((uint4*)out)[i] = u;
}

__global__ void rope_tab_kernel()
{
    int i = blockIdx.x * blockDim.x + threadIdx.x;
    if (i >= POSMAX * 16) return;
    int pos = i >> 4, f = i & 15;
    float inv = exp2f(-0.41524101186f * (float)f);  // 100^(-f/16)
    float s, c;
    sincosf((float)pos * inv, &s, &c);
    g_rope_tab[i] = make_float2(c, s);
}

// ---------------------------------------------------------------------------
// FP16-input tensor-core GEMM (fp32 accumulate), R11/R14-measured geometry:
// block 128x128, BK=32, 256 threads = 8 warps (2m x 4n), warp tile 64x32,
// double-buffered smem. ROPE=true: fused bias + table RoPE2D -> fp16 q/k/v.
// ---------------------------------------------------------------------------
#define BKh 32
#define SSTRH 40
#define SA_H (128 * SSTRH)

template <bool ROPE>
__global__ void __launch_bounds__(256, 2) gemm_k(
    const __half* __restrict__ A, const __half* __restrict__ W,
    const float* __restrict__ bias, float* __restrict__ outf,
    const int* __restrict__ pos2d, int M, int Nout, int K)
{
    __shared__ __align__(16) __half sA[2][SA_H];
    __shared__ __align__(16) __half sB[2][SA_H];

    const int t = threadIdx.x;
    const int lane = t & 31;
    const int warp = t >> 5;
    const int wm = (warp & 1) * 64;
    const int wn = (warp >> 1) * 32;
    const int m0 = blockIdx.y * 128;
    const int n0 = blockIdx.x * 128;

    int rg[4], cg[4];
#pragma unroll
    for (int i = 0; i < 4; i++) { rg[i] = (t + i * 256) >> 3; cg[i] = ((t + i * 256) & 7) * 4; }

    const int lg = lane >> 3, lr = lane & 7;
    const int a_off = ((lg & 1) * 8 + lr) * SSTRH + (lg >> 1) * 8;
    const int b_off = ((lg >> 1) * 8 + lr) * SSTRH + (lg & 1) * 8;

    float acc[4][4][4];
#pragma unroll
    for (int i = 0; i < 4; i++)
#pragma unroll
        for (int j = 0; j < 4; j++)
#pragma unroll
            for (int v = 0; v < 4; v++) acc[i][j][v] = 0.f;

    const int fr = lane >> 2;
    const int fc = lane & 3;

    uint2 qa[4], qb[4];
#pragma unroll
    for (int i = 0; i < 4; i++) {
        qa[i] = *(const uint2*)(A + (size_t)(m0 + rg[i]) * K + cg[i]);
        qb[i] = *(const uint2*)(W + (size_t)(n0 + rg[i]) * K + cg[i]);
    }
#pragma unroll
    for (int i = 0; i < 4; i++) {
        *(uint2*)&sA[0][rg[i] * SSTRH + cg[i]] = qa[i];
        *(uint2*)&sB[0][rg[i] * SSTRH + cg[i]] = qb[i];
    }
    __syncthreads();

    const int nIter = K / BKh;
    for (int it = 0; it < nIter; it++) {
        const int buf = it & 1;
        const bool has_next = (it + 1) < nIter;

        if (has_next) {
            int kn = (it + 1) * BKh;
#pragma unroll
            for (int i = 0; i < 4; i++) {
                qa[i] = *(const uint2*)(A + (size_t)(m0 + rg[i]) * K + kn + cg[i]);
                qb[i] = *(const uint2*)(W + (size_t)(n0 + rg[i]) * K + kn + cg[i]);
            }
        }

        const __half* cA = sA[buf];
        const __half* cB = sB[buf];
#pragma unroll
        for (int ks = 0; ks < 2; ks++) {
            unsigned areg[4][4], breg[4][2];
#pragma unroll
            for (int mf = 0; mf < 4; mf++)
                ldsm_x4(areg[mf][0], areg[mf][1], areg[mf][2], areg[mf][3],
                        sptr(cA + (wm + mf * 16) * SSTRH + ks * 16 + a_off));
#pragma unroll
            for (int np = 0; np < 2; np++)
                ldsm_x4(breg[np * 2][0], breg[np * 2][1],
                        breg[np * 2 + 1][0], breg[np * 2 + 1][1],
                        sptr(cB + (wn + np * 16) * SSTRH + ks * 16 + b_off));
#pragma unroll
            for (int mf = 0; mf < 4; mf++)
#pragma unroll
                for (int nf = 0; nf < 4; nf++)
                    mma_f16(acc[mf][nf], areg[mf], breg[nf]);
        }

        if (has_next) {
#pragma unroll
            for (int i = 0; i < 4; i++) {
                *(uint2*)&sA[buf ^ 1][rg[i] * SSTRH + cg[i]] = qa[i];
                *(uint2*)&sB[buf ^ 1][rg[i] * SSTRH + cg[i]] = qb[i];
            }
            __syncthreads();
        }
    }

    if (!ROPE) {
#pragma unroll
        for (int mf = 0; mf < 4; mf++) {
            int row = m0 + wm + mf * 16 + fr;
#pragma unroll
            for (int nf = 0; nf < 4; nf++) {
                int col = n0 + wn + nf * 8 + 2 * fc;
                float bx = bias[col], by = bias[col + 1];
                *(float2*)(outf + (size_t)row * Nout + col) =
                    make_float2(acc[mf][nf][0] + bx, acc[mf][nf][1] + by);
                *(float2*)(outf + (size_t)(row + 8) * Nout + col) =
                    make_float2(acc[mf][nf][2] + bx, acc[mf][nf][3] + by);
            }
        }
    } else {
        const int colbase = n0 + wn;
        const int third = colbase / C_;          // 0=q, 1=k, 2=v
        const int cw = colbase - third * C_;
        const int h = cw >> 6;
        const int half01 = (cw >> 5) & 1;        // 0=y-half, 1=x-half
        __half* dst = (third == 0) ? g_qh : (third == 1) ? g_kh : g_vh;

#pragma unroll
        for (int mf = 0; mf < 4; mf++) {
#pragma unroll
            for (int rh = 0; rh < 2; rh++) {
                int row = m0 + wm + mf * 16 + fr + rh * 8;
                int b = row >> 10, n = row & 1023;
                float v[4][2], o[4][2];
#pragma unroll
                for (int nf = 0; nf < 4; nf++) {
                    int col = colbase + nf * 8 + 2 * fc;
                    v[nf][0] = acc[mf][nf][rh * 2 + 0] + bias[col];
                    v[nf][1] = acc[mf][nf][rh * 2 + 1] + bias[col + 1];
                }
                if (third != 2 && n < NIMG_) {
                    int pos = pos2d[((size_t)b * NIMG_ + n) * 2 + half01];
                    const float2* tab = g_rope_tab + pos * 16;
#pragma unroll
                    for (int nf = 0; nf < 2; nf++) {
#pragma unroll
                        for (int j = 0; j < 2; j++) {
                            int f = nf * 8 + 2 * fc + j;   // 0..15
                            float2 cs = tab[f];
                            o[nf][j]     = v[nf][j] * cs.x - v[nf + 2][j] * cs.y;
                            o[nf + 2][j] = v[nf + 2][j] * cs.x + v[nf][j] * cs.y;
                        }
                    }
                } else {
#pragma unroll
                    for (int nf = 0; nf < 4; nf++) {
                        o[nf][0] = v[nf][0]; o[nf][1] = v[nf][1];
                    }
                }
                size_t base = ((size_t)(b * H_ + h) * N_ + n) * DH_ + half01 * 32;
#pragma unroll
                for (int nf = 0; nf < 4; nf++) {
                    int i = nf * 8 + 2 * fc;
                    *(unsigned*)(dst + base + i) = packh2(o[nf][0], o[nf][1]);
                }
            }
        }
    }
}

// ---------------------------------------------------------------------------
// FP16 flash attention, BQ=128. Grid: (N/128, B*H). 256 threads = 8 warps,
// warp w owns q-rows [16w, 16w+16) — per-warp mainloop identical to R14/R15.
// smem: sQ[128] sK[64] sV[64] sP[128] rows x 72 halves.
// ---------------------------------------------------------------------------
#define ASTRH 72
#define ATTN_SMEM_BYTES ((128 + 64 + 64 + 128) * ASTRH * 2)

__global__ void __launch_bounds__(256) attn_mma_kernel(__half* __restrict__ out)
{
    extern __shared__ __align__(16) __half smh[];
    __half* sQ = smh;                         // 128 rows
    __half* sK = smh + 128 * ASTRH;           // 64 rows
    __half* sV = smh + (128 + 64) * ASTRH;    // 64 rows [key][d]
    __half* sP = smh + (128 + 128) * ASTRH;   // 128 rows

    const int t = threadIdx.x;
    const int lane = t & 31;
    const int w = t >> 5;
    const int fr = lane >> 2;
    const int fc = lane & 3;
    const int wm = w * 16;
    const int bh = blockIdx.y;
    const int q0 = blockIdx.x * 128;

    const int lg = lane >> 3, lr = lane & 7;
    const int a_off = ((lg & 1) * 8 + lr) * ASTRH + (lg >> 1) * 8;
    const int b_off = ((lg >> 1) * 8 + lr) * ASTRH + (lg & 1) * 8;

    const __half* Qg = g_qh + ((size_t)bh * N_ + q0) * DH_;
    const __half* Kg = g_kh + (size_t)bh * N_ * DH_;
    const __half* Vg = g_vh + (size_t)bh * N_ * DH_;

    // Q tile 128x64 halves = 1024 uint4, 4 per thread
#pragma unroll
    for (int i = 0; i < 4; i++) {
        int idx8 = t + i * 256;
        int r = idx8 >> 3;
        int c8 = (idx8 & 7) * 8;
        *(uint4*)&sQ[r * ASTRH + c8] = *(const uint4*)(Qg + (size_t)r * 64 + c8);
    }

    float m0 = -1e30f, m1 = -1e30f, l0 = 0.f, l1 = 0.f;
    float oacc[8][4];
#pragma unroll
    for (int nf = 0; nf < 8; nf++)
#pragma unroll
        for (int v = 0; v < 4; v++) oacc[nf][v] = 0.f;

    for (int kb = 0; kb < N_; kb += 64) {
        if (kb) __syncthreads();
        // K/V tiles 64x64 halves = 512 uint4 each, 2 per thread
#pragma unroll
        for (int i = 0; i < 2; i++) {
            int idx8 = t + i * 256;
            int r = idx8 >> 3;
            int c8 = (idx8 & 7) * 8;
            *(uint4*)&sK[r * ASTRH + c8] = *(const uint4*)(Kg + (size_t)(kb + r) * 64 + c8);
            *(uint4*)&sV[r * ASTRH + c8] = *(const uint4*)(Vg + (size_t)(kb + r) * 64 + c8);
        }
        __syncthreads();

        // S = Q K^T : 4 k16 steps
        float sacc[8][4];
#pragma unroll
        for (int nf = 0; nf < 8; nf++)
#pragma unroll
            for (int v = 0; v < 4; v++) sacc[nf][v] = 0.f;
#pragma unroll
        for (int kc = 0; kc < 4; kc++) {
            unsigned a[4], breg[8][2];
            ldsm_x4(a[0], a[1], a[2], a[3], sptr(sQ + wm * ASTRH + kc * 16 + a_off));
#pragma unroll
            for (int np = 0; np < 4; np++)
                ldsm_x4(breg[np * 2][0], breg[np * 2][1],
                        breg[np * 2 + 1][0], breg[np * 2 + 1][1],
                        sptr(sK + np * 16 * ASTRH + kc * 16 + b_off));
#pragma unroll
            for (int nf = 0; nf < 8; nf++)
                mma_f16(sacc[nf], a, breg[nf]);
        }

        const float scale = 0.125f;
        float rm0 = -1e30f, rm1 = -1e30f;
#pragma unroll
        for (int nf = 0; nf < 8; nf++) {
#pragma unroll
            for (int v = 0; v < 4; v++) sacc[nf][v] *= scale;
            rm0 = fmaxf(rm0, fmaxf(sacc[nf][0], sacc[nf][1]));
            rm1 = fmaxf(rm1, fmaxf(sacc[nf][2], sacc[nf][3]));
        }
#pragma unroll
        for (int off = 1; off < 4; off <<= 1) {
            rm0 = fmaxf(rm0, __shfl_xor_sync(0xffffffffu, rm0, off));
            rm1 = fmaxf(rm1, __shfl_xor_sync(0xffffffffu, rm1, off));
        }
        float mn0 = fmaxf(m0, rm0), mn1 = fmaxf(m1, rm1);
        float corr0 = __expf(m0 - mn0), corr1 = __expf(m1 - mn1);
        m0 = mn0; m1 = mn1;
        float rs0 = 0.f, rs1 = 0.f;
#pragma unroll
        for (int nf = 0; nf < 8; nf++) {
            float p0 = __expf(sacc[nf][0] - mn0);
            float p1 = __expf(sacc[nf][1] - mn0);
            float p2 = __expf(sacc[nf][2] - mn1);
            float p3 = __expf(sacc[nf][3] - mn1);
            sacc[nf][0] = p0; sacc[nf][1] = p1; sacc[nf][2] = p2; sacc[nf][3] = p3;
            rs0 += p0 + p1; rs1 += p2 + p3;
        }
#pragma unroll
        for (int off = 1; off < 4; off <<= 1) {
            rs0 += __shfl_xor_sync(0xffffffffu, rs0, off);
            rs1 += __shfl_xor_sync(0xffffffffu, rs1, off);
        }
        l0 = l0 * corr0 + rs0;
        l1 = l1 * corr1 + rs1;
#pragma unroll
        for (int nf = 0; nf < 8; nf++) {
            oacc[nf][0] *= corr0; oacc[nf][1] *= corr0;
            oacc[nf][2] *= corr1; oacc[nf][3] *= corr1;
        }

        // P -> sP as fp16 (warp-private rows)
#pragma unroll
        for (int nf = 0; nf < 8; nf++) {
            *(unsigned*)&sP[(wm + fr) * ASTRH + nf * 8 + 2 * fc] =
                packh2(sacc[nf][0], sacc[nf][1]);
            *(unsigned*)&sP[(wm + fr + 8) * ASTRH + nf * 8 + 2 * fc] =
                packh2(sacc[nf][2], sacc[nf][3]);
        }
        __syncwarp();

        // O += P V : B-fragments via ldmatrix.trans on row-major sV[key][d]
#pragma unroll
        for (int kc = 0; kc < 4; kc++) {
            unsigned a[4], breg[8][2];
            ldsm_x4(a[0], a[1], a[2], a[3], sptr(sP + wm * ASTRH + kc * 16 + a_off));
#pragma unroll
            for (int np = 0; np < 4; np++)
                ldsm_x4_t(breg[np * 2][0], breg[np * 2][1],
                          breg[np * 2 + 1][0], breg[np * 2 + 1][1],
                          sptr(sV + kc * 16 * ASTRH + np * 16 + a_off));
#pragma unroll
            for (int nf = 0; nf < 8; nf++)
                mma_f16(oacc[nf], a, breg[nf]);
        }
    }

    const float inv0 = 1.0f / l0;
    const float inv1 = 1.0f / l1;
    const int b = bh / H_;
    const int h = bh % H_;
    const int r0 = q0 + wm + fr;
#pragma unroll
    for (int nf = 0; nf < 8; nf++) {
        int col = h * 64 + nf * 8 + 2 * fc;
        *(unsigned*)(out + (size_t)(b * N_ + r0) * C_ + col) =
            packh2(oacc[nf][0] * inv0, oacc[nf][1] * inv0);
        *(unsigned*)(out + (size_t)(b * N_ + r0 + 8) * C_ + col) =
            packh2(oacc[nf][2] * inv1, oacc[nf][3] * inv1);
    }
}

// ---------------------------------------------------------------------------
extern "C" void kernel_launch(void* const* d_in, const int* in_sizes, int n_in,
                              void* d_out, int out_size)
{
    const float* x_t    = (const float*)d_in[0];
    const float* qkv_w  = (const float*)d_in[1];
    const float* qkv_b  = (const float*)d_in[2];
    const float* proj_w = (const float*)d_in[3];
    const float* proj_b = (const float*)d_in[4];
    const int*   pos2d  = (const int*)d_in[5];
    float* out = (float*)d_out;

    __half *p_x, *p_qkvw, *p_projw, *p_aoh;
    cudaGetSymbolAddress((void**)&p_x, gh_x);
    cudaGetSymbolAddress((void**)&p_qkvw, gh_qkvw);
    cudaGetSymbolAddress((void**)&p_projw, gh_projw);
    cudaGetSymbolAddress((void**)&p_aoh, g_aoh);

    cudaFuncSetAttribute(attn_mma_kernel,
                         cudaFuncAttributeMaxDynamicSharedMemorySize,
                         ATTN_SMEM_BYTES);

    // 0) setup: f32->f16 inputs + RoPE sincos table
    {
        int nx = B_ * N_ * C_ / 8;
        f2h_kernel<<<(nx + 255) / 256, 256>>>(x_t, p_x, nx);
        int nw = 3 * C_ * C_ / 8;
        f2h_kernel<<<(nw + 255) / 256, 256>>>(qkv_w, p_qkvw, nw);
        int np = C_ * C_ / 8;
        f2h_kernel<<<(np + 255) / 256, 256>>>(proj_w, p_projw, np);
        rope_tab_kernel<<<2, 256>>>();
    }
    // 1) QKV GEMM + fused bias + RoPE2D(table) + split -> fp16 q/k/v
    {
        dim3 grid((3 * C_) / 128, (B_ * N_) / 128);
        gemm_k<true><<<grid, 256>>>(p_x, p_qkvw, qkv_b, nullptr, pos2d,
                                    B_ * N_, 3 * C_, C_);
    }
    // 2) Attention (fp16 MMA, BQ=128) -> fp16 g_aoh
    {
        dim3 grid(N_ / 128, B_ * H_);
        attn_mma_kernel<<<grid, 256, ATTN_SMEM_BYTES>>>(p_aoh);
    }
    // 3) Output projection (fp16 in, f32 out): [8192,768] x [768,768]^T
    {
        dim3 grid(C_ / 128, (B_ * N_) / 128);
        gemm_k<false><<<grid, 256>>>(p_aoh, p_projw, proj_b, out, nullptr,
                                     B_ * N_, C_, C_);
    }
}

// round 17
// speedup vs baseline: 1.8523x; 1.0141x over previous
#include <cuda_runtime.h>
#include <cuda_fp16.h>
#include <cstdint>
#include <stdint.h>
#include <math.h>

#define B_ 8
#define N_ 1024
#define C_ 768
#define H_ 12
#define DH_ 64
#define NIMG_ 784
#define POSMAX 28

// Scratch (static device arrays: allocation-free per harness rules)
__device__ __half gh_x[B_ * N_ * C_];           // x_t fp16
__device__ __half gh_qkvw[3 * C_ * C_];         // qkv_w fp16
__device__ __half gh_projw[C_ * C_];            // proj_w fp16
__device__ __half g_qh[B_ * H_ * N_ * DH_];     // [bh][n][d] fp16
__device__ __half g_kh[B_ * H_ * N_ * DH_];
__device__ __half g_vh[B_ * H_ * N_ * DH_];
__device__ __half g_aoh[B_ * N_ * C_];          // attention out fp16
__device__ float2 g_rope_tab[POSMAX * 16];      // (cos, sin) per (pos, f)

__device__ __forceinline__ unsigned packh2(float a, float b) {
    __half2 h = __floats2half2_rn(a, b);
    return *(unsigned*)&h;
}

__device__ __forceinline__ void mma_f16(float* d, const unsigned* a, const unsigned* b) {
    asm volatile(
        "mma.sync.aligned.m16n8k16.row.col.f32.f16.f16.f32 "
        "{%0,%1,%2,%3}, {%4,%5,%6,%7}, {%8,%9}, {%0,%1,%2,%3};"
        : "+f"(d[0]), "+f"(d[1]), "+f"(d[2]), "+f"(d[3])
        : "r"(a[0]), "r"(a[1]), "r"(a[2]), "r"(a[3]), "r"(b[0]), "r"(b[1]));
}

__device__ __forceinline__ unsigned sptr(const void* p) {
    return (unsigned)__cvta_generic_to_shared(p);
}

__device__ __forceinline__ void ldsm_x4(unsigned& r0, unsigned& r1,
                                        unsigned& r2, unsigned& r3, unsigned addr) {
    asm volatile("ldmatrix.sync.aligned.m8n8.x4.shared.b16 {%0,%1,%2,%3}, [%4];"
        : "=r"(r0), "=r"(r1), "=r"(r2), "=r"(r3) : "r"(addr));
}

__device__ __forceinline__ void ldsm_x4_t(unsigned& r0, unsigned& r1,
                                          unsigned& r2, unsigned& r3, unsigned addr) {
    asm volatile("ldmatrix.sync.aligned.m8n8.x4.trans.shared.b16 {%0,%1,%2,%3}, [%4];"
        : "=r"(r0), "=r"(r1), "=r"(r2), "=r"(r3) : "r"(addr));
}

__device__ __forceinline__ void cp_async16(unsigned smaddr, const void* gptr) {
    asm volatile("cp.async.cg.shared.global [%0], [%1], 16;"
                 :: "r"(smaddr), "l"(gptr) : "memory");
}
template <int NN>
__device__ __forceinline__ void cp_wait() {
    asm volatile("cp.async.wait_group %0;" :: "n"(NN) : "memory");
}
__device__ __forceinline__ void cp_commit() {
    asm volatile("cp.async.commit_group;" ::: "memory");
}

// ---------------------------------------------------------------------------
// Setup kernels: f32->f16 convert; RoPE sincos table
// ---------------------------------------------------------------------------
__global__ void f2h_kernel(const float* __restrict__ in, __half* __restrict__ out, int n8)
{
    int i = blockIdx.x * blockDim.x + threadIdx.x;
    if (i >= n8) return;
    float4 a = ((const float4*)in)[i * 2];
    float4 b = ((const float4*)in)[i * 2 + 1];
    uint4 u;
    u.x = packh2(a.x, a.y); u.y = packh2(a.z, a.w);
    u.z = packh2(b.x, b.y); u.w = packh2(b.z, b.w);
    ((uint4*)out)[i] = u;
}

__global__ void rope_tab_kernel()
{
    int i = blockIdx.x * blockDim.x + threadIdx.x;
    if (i >= POSMAX * 16) return;
    int pos = i >> 4, f = i & 15;
    float inv = exp2f(-0.41524101186f * (float)f);  // 100^(-f/16)
    float s, c;
    sincosf((float)pos * inv, &s, &c);
    g_rope_tab[i] = make_float2(c, s);
}

// ---------------------------------------------------------------------------
// FP16-input tensor-core GEMM (fp32 accumulate), R11/R14-measured geometry:
// block 128x128, BK=32, 256 threads = 8 warps (2m x 4n), warp tile 64x32,
// double-buffered smem. ROPE=true: fused bias + table RoPE2D -> fp16 q/k/v.
// ---------------------------------------------------------------------------
#define BKh 32
#define SSTRH 40
#define SA_H (128 * SSTRH)

template <bool ROPE>
__global__ void __launch_bounds__(256, 2) gemm_k(
    const __half* __restrict__ A, const __half* __restrict__ W,
    const float* __restrict__ bias, float* __restrict__ outf,
    const int* __restrict__ pos2d, int M, int Nout, int K)
{
    __shared__ __align__(16) __half sA[2][SA_H];
    __shared__ __align__(16) __half sB[2][SA_H];

    const int t = threadIdx.x;
    const int lane = t & 31;
    const int warp = t >> 5;
    const int wm = (warp & 1) * 64;
    const int wn = (warp >> 1) * 32;
    const int m0 = blockIdx.y * 128;
    const int n0 = blockIdx.x * 128;

    int rg[4], cg[4];
#pragma unroll
    for (int i = 0; i < 4; i++) { rg[i] = (t + i * 256) >> 3; cg[i] = ((t + i * 256) & 7) * 4; }

    const int lg = lane >> 3, lr = lane & 7;
    const int a_off = ((lg & 1) * 8 + lr) * SSTRH + (lg >> 1) * 8;
    const int b_off = ((lg >> 1) * 8 + lr) * SSTRH + (lg & 1) * 8;

    float acc[4][4][4];
#pragma unroll
    for (int i = 0; i < 4; i++)
#pragma unroll
        for (int j = 0; j < 4; j++)
#pragma unroll
            for (int v = 0; v < 4; v++) acc[i][j][v] = 0.f;

    const int fr = lane >> 2;
    const int fc = lane & 3;

    uint2 qa[4], qb[4];
#pragma unroll
    for (int i = 0; i < 4; i++) {
        qa[i] = *(const uint2*)(A + (size_t)(m0 + rg[i]) * K + cg[i]);
        qb[i] = *(const uint2*)(W + (size_t)(n0 + rg[i]) * K + cg[i]);
    }
#pragma unroll
    for (int i = 0; i < 4; i++) {
        *(uint2*)&sA[0][rg[i] * SSTRH + cg[i]] = qa[i];
        *(uint2*)&sB[0][rg[i] * SSTRH + cg[i]] = qb[i];
    }
    __syncthreads();

    const int nIter = K / BKh;
    for (int it = 0; it < nIter; it++) {
        const int buf = it & 1;
        const bool has_next = (it + 1) < nIter;

        if (has_next) {
            int kn = (it + 1) * BKh;
#pragma unroll
            for (int i = 0; i < 4; i++) {
                qa[i] = *(const uint2*)(A + (size_t)(m0 + rg[i]) * K + kn + cg[i]);
                qb[i] = *(const uint2*)(W + (size_t)(n0 + rg[i]) * K + kn + cg[i]);
            }
        }

        const __half* cA = sA[buf];
        const __half* cB = sB[buf];
#pragma unroll
        for (int ks = 0; ks < 2; ks++) {
            unsigned areg[4][4], breg[4][2];
#pragma unroll
            for (int mf = 0; mf < 4; mf++)
                ldsm_x4(areg[mf][0], areg[mf][1], areg[mf][2], areg[mf][3],
                        sptr(cA + (wm + mf * 16) * SSTRH + ks * 16 + a_off));
#pragma unroll
            for (int np = 0; np < 2; np++)
                ldsm_x4(breg[np * 2][0], breg[np * 2][1],
                        breg[np * 2 + 1][0], breg[np * 2 + 1][1],
                        sptr(cB + (wn + np * 16) * SSTRH + ks * 16 + b_off));
#pragma unroll
            for (int mf = 0; mf < 4; mf++)
#pragma unroll
                for (int nf = 0; nf < 4; nf++)
                    mma_f16(acc[mf][nf], areg[mf], breg[nf]);
        }

        if (has_next) {
#pragma unroll
            for (int i = 0; i < 4; i++) {
                *(uint2*)&sA[buf ^ 1][rg[i] * SSTRH + cg[i]] = qa[i];
                *(uint2*)&sB[buf ^ 1][rg[i] * SSTRH + cg[i]] = qb[i];
            }
            __syncthreads();
        }
    }

    if (!ROPE) {
#pragma unroll
        for (int mf = 0; mf < 4; mf++) {
            int row = m0 + wm + mf * 16 + fr;
#pragma unroll
            for (int nf = 0; nf < 4; nf++) {
                int col = n0 + wn + nf * 8 + 2 * fc;
                float bx = bias[col], by = bias[col + 1];
                *(float2*)(outf + (size_t)row * Nout + col) =
                    make_float2(acc[mf][nf][0] + bx, acc[mf][nf][1] + by);
                *(float2*)(outf + (size_t)(row + 8) * Nout + col) =
                    make_float2(acc[mf][nf][2] + bx, acc[mf][nf][3] + by);
            }
        }
    } else {
        const int colbase = n0 + wn;
        const int third = colbase / C_;          // 0=q, 1=k, 2=v
        const int cw = colbase - third * C_;
        const int h = cw >> 6;
        const int half01 = (cw >> 5) & 1;        // 0=y-half, 1=x-half
        __half* dst = (third == 0) ? g_qh : (third == 1) ? g_kh : g_vh;

#pragma unroll
        for (int mf = 0; mf < 4; mf++) {
#pragma unroll
            for (int rh = 0; rh < 2; rh++) {
                int row = m0 + wm + mf * 16 + fr + rh * 8;
                int b = row >> 10, n = row & 1023;
                float v[4][2], o[4][2];
#pragma unroll
                for (int nf = 0; nf < 4; nf++) {
                    int col = colbase + nf * 8 + 2 * fc;
                    v[nf][0] = acc[mf][nf][rh * 2 + 0] + bias[col];
                    v[nf][1] = acc[mf][nf][rh * 2 + 1] + bias[col + 1];
                }
                if (third != 2 && n < NIMG_) {
                    int pos = pos2d[((size_t)b * NIMG_ + n) * 2 + half01];
                    const float2* tab = g_rope_tab + pos * 16;
#pragma unroll
                    for (int nf = 0; nf < 2; nf++) {
#pragma unroll
                        for (int j = 0; j < 2; j++) {
                            int f = nf * 8 + 2 * fc + j;   // 0..15
                            float2 cs = tab[f];
                            o[nf][j]     = v[nf][j] * cs.x - v[nf + 2][j] * cs.y;
                            o[nf + 2][j] = v[nf + 2][j] * cs.x + v[nf][j] * cs.y;
                        }
                    }
                } else {
#pragma unroll
                    for (int nf = 0; nf < 4; nf++) {
                        o[nf][0] = v[nf][0]; o[nf][1] = v[nf][1];
                    }
                }
                size_t base = ((size_t)(b * H_ + h) * N_ + n) * DH_ + half01 * 32;
#pragma unroll
                for (int nf = 0; nf < 4; nf++) {
                    int i = nf * 8 + 2 * fc;
                    *(unsigned*)(dst + base + i) = packh2(o[nf][0], o[nf][1]);
                }
            }
        }
    }
}

// ---------------------------------------------------------------------------
// FP16 flash attention, BQ=128, cp.async double-buffered K/V pipeline.
// Grid: (N/128, B*H). 256 threads = 8 warps, warp w owns q-rows [16w,16w+16).
// smem rows (x72 halves): Q[0..128) K0[128..192) V0[192..256)
//                         K1[256..320) V1[320..384) P[384..512)
// ---------------------------------------------------------------------------
#define ASTRH 72
#define ATTN_SMEM_BYTES (512 * ASTRH * 2)

__global__ void __launch_bounds__(256) attn_mma_kernel(__half* __restrict__ out)
{
    extern __shared__ __align__(16) __half smh[];
    __half* sQ = smh;
    __half* sKV[2] = { smh + 128 * ASTRH, smh + 256 * ASTRH };  // K then V, 64 rows each
    __half* sP = smh + 384 * ASTRH;

    const int t = threadIdx.x;
    const int lane = t & 31;
    const int w = t >> 5;
    const int fr = lane >> 2;
    const int fc = lane & 3;
    const int wm = w * 16;
    const int bh = blockIdx.y;
    const int q0 = blockIdx.x * 128;

    const int lg = lane >> 3, lr = lane & 7;
    const int a_off = ((lg & 1) * 8 + lr) * ASTRH + (lg >> 1) * 8;
    const int b_off = ((lg >> 1) * 8 + lr) * ASTRH + (lg & 1) * 8;

    const __half* Qg = g_qh + ((size_t)bh * N_ + q0) * DH_;
    const __half* Kg = g_kh + (size_t)bh * N_ * DH_;
    const __half* Vg = g_vh + (size_t)bh * N_ * DH_;

    // K/V loader mapping: 2 x 16B per thread per tile
    const int kr0 = t >> 3, kc0 = (t & 7) * 8;            // rows 0..31
    const int kr1 = (t + 256) >> 3, kc1 = kc0;            // rows 32..63

    // Q tile 128x64 halves = 1024 uint4, 4 per thread
#pragma unroll
    for (int i = 0; i < 4; i++) {
        int idx8 = t + i * 256;
        int r = idx8 >> 3;
        int c8 = (idx8 & 7) * 8;
        *(uint4*)&sQ[r * ASTRH + c8] = *(const uint4*)(Qg + (size_t)r * 64 + c8);
    }

    // prologue: cp.async block 0 into buf 0
    {
        __half* dK = sKV[0];
        __half* dV = sKV[0] + 64 * ASTRH;
        cp_async16(sptr(dK + kr0 * ASTRH + kc0), Kg + (size_t)kr0 * 64 + kc0);
        cp_async16(sptr(dK + kr1 * ASTRH + kc1), Kg + (size_t)kr1 * 64 + kc1);
        cp_async16(sptr(dV + kr0 * ASTRH + kc0), Vg + (size_t)kr0 * 64 + kc0);
        cp_async16(sptr(dV + kr1 * ASTRH + kc1), Vg + (size_t)kr1 * 64 + kc1);
        cp_commit();
    }

    float m0 = -1e30f, m1 = -1e30f, l0 = 0.f, l1 = 0.f;
    float oacc[8][4];
#pragma unroll
    for (int nf = 0; nf < 8; nf++)
#pragma unroll
        for (int v = 0; v < 4; v++) oacc[nf][v] = 0.f;

    const int nBlocks = N_ / 64;
    for (int ib = 0; ib < nBlocks; ib++) {
        const int buf = ib & 1;

        if (ib + 1 < nBlocks) {
            size_t kb2 = (size_t)(ib + 1) * 64;
            __half* dK = sKV[buf ^ 1];
            __half* dV = sKV[buf ^ 1] + 64 * ASTRH;
            cp_async16(sptr(dK + kr0 * ASTRH + kc0), Kg + (kb2 + kr0) * 64 + kc0);
            cp_async16(sptr(dK + kr1 * ASTRH + kc1), Kg + (kb2 + kr1) * 64 + kc1);
            cp_async16(sptr(dV + kr0 * ASTRH + kc0), Vg + (kb2 + kr0) * 64 + kc0);
            cp_async16(sptr(dV + kr1 * ASTRH + kc1), Vg + (kb2 + kr1) * 64 + kc1);
            cp_commit();
            cp_wait<1>();   // current block's group complete
        } else {
            cp_wait<0>();
        }
        __syncthreads();

        const __half* sK = sKV[buf];
        const __half* sV = sKV[buf] + 64 * ASTRH;

        // S = Q K^T : 4 k16 steps
        float sacc[8][4];
#pragma unroll
        for (int nf = 0; nf < 8; nf++)
#pragma unroll
            for (int v = 0; v < 4; v++) sacc[nf][v] = 0.f;
#pragma unroll
        for (int kc = 0; kc < 4; kc++) {
            unsigned a[4], breg[8][2];
            ldsm_x4(a[0], a[1], a[2], a[3], sptr(sQ + wm * ASTRH + kc * 16 + a_off));
#pragma unroll
            for (int np = 0; np < 4; np++)
                ldsm_x4(breg[np * 2][0], breg[np * 2][1],
                        breg[np * 2 + 1][0], breg[np * 2 + 1][1],
                        sptr(sK + np * 16 * ASTRH + kc * 16 + b_off));
#pragma unroll
            for (int nf = 0; nf < 8; nf++)
                mma_f16(sacc[nf], a, breg[nf]);
        }

        const float scale = 0.125f;
        float rm0 = -1e30f, rm1 = -1e30f;
#pragma unroll
        for (int nf = 0; nf < 8; nf++) {
#pragma unroll
            for (int v = 0; v < 4; v++) sacc[nf][v] *= scale;
            rm0 = fmaxf(rm0, fmaxf(sacc[nf][0], sacc[nf][1]));
            rm1 = fmaxf(rm1, fmaxf(sacc[nf][2], sacc[nf][3]));
        }
#pragma unroll
        for (int off = 1; off < 4; off <<= 1) {
            rm0 = fmaxf(rm0, __shfl_xor_sync(0xffffffffu, rm0, off));
            rm1 = fmaxf(rm1, __shfl_xor_sync(0xffffffffu, rm1, off));
        }
        float mn0 = fmaxf(m0, rm0), mn1 = fmaxf(m1, rm1);
        float corr0 = __expf(m0 - mn0), corr1 = __expf(m1 - mn1);
        m0 = mn0; m1 = mn1;
        float rs0 = 0.f, rs1 = 0.f;
#pragma unroll
        for (int nf = 0; nf < 8; nf++) {
            float p0 = __expf(sacc[nf][0] - mn0);
            float p1 = __expf(sacc[nf][1] - mn0);
            float p2 = __expf(sacc[nf][2] - mn1);
            float p3 = __expf(sacc[nf][3] - mn1);
            sacc[nf][0] = p0; sacc[nf][1] = p1; sacc[nf][2] = p2; sacc[nf][3] = p3;
            rs0 += p0 + p1; rs1 += p2 + p3;
        }
#pragma unroll
        for (int off = 1; off < 4; off <<= 1) {
            rs0 += __shfl_xor_sync(0xffffffffu, rs0, off);
            rs1 += __shfl_xor_sync(0xffffffffu, rs1, off);
        }
        l0 = l0 * corr0 + rs0;
        l1 = l1 * corr1 + rs1;
#pragma unroll
        for (int nf = 0; nf < 8; nf++) {
            oacc[nf][0] *= corr0; oacc[nf][1] *= corr0;
            oacc[nf][2] *= corr1; oacc[nf][3] *= corr1;
        }

        // P -> sP as fp16 (warp-private rows)
#pragma unroll
        for (int nf = 0; nf < 8; nf++) {
            *(unsigned*)&sP[(wm + fr) * ASTRH + nf * 8 + 2 * fc] =
                packh2(sacc[nf][0], sacc[nf][1]);
            *(unsigned*)&sP[(wm + fr + 8) * ASTRH + nf * 8 + 2 * fc] =
                packh2(sacc[nf][2], sacc[nf][3]);
        }
        __syncwarp();

        // O += P V : B-fragments via ldmatrix.trans on row-major sV[key][d]
#pragma unroll
        for (int kc = 0; kc < 4; kc++) {
            unsigned a[4], breg[8][2];
            ldsm_x4(a[0], a[1], a[2], a[3], sptr(sP + wm * ASTRH + kc * 16 + a_off));
#pragma unroll
            for (int np = 0; np < 4; np++)
                ldsm_x4_t(breg[np * 2][0], breg[np * 2][1],
                          breg[np * 2 + 1][0], breg[np * 2 + 1][1],
                          sptr(sV + kc * 16 * ASTRH + np * 16 + a_off));
#pragma unroll
            for (int nf = 0; nf < 8; nf++)
                mma_f16(oacc[nf], a, breg[nf]);
        }
        __syncthreads();   // buf may be re-targeted by cp.async next iter
    }

    const float inv0 = 1.0f / l0;
    const float inv1 = 1.0f / l1;
    const int b = bh / H_;
    const int h = bh % H_;
    const int r0 = q0 + wm + fr;
#pragma unroll
    for (int nf = 0; nf < 8; nf++) {
        int col = h * 64 + nf * 8 + 2 * fc;
        *(unsigned*)(out + (size_t)(b * N_ + r0) * C_ + col) =
            packh2(oacc[nf][0] * inv0, oacc[nf][1] * inv0);
        *(unsigned*)(out + (size_t)(b * N_ + r0 + 8) * C_ + col) =
            packh2(oacc[nf][2] * inv1, oacc[nf][3] * inv1);
    }
}

// ---------------------------------------------------------------------------
extern "C" void kernel_launch(void* const* d_in, const int* in_sizes, int n_in,
                              void* d_out, int out_size)
{
    const float* x_t    = (const float*)d_in[0];
    const float* qkv_w  = (const float*)d_in[1];
    const float* qkv_b  = (const float*)d_in[2];
    const float* proj_w = (const float*)d_in[3];
    const float* proj_b = (const float*)d_in[4];
    const int*   pos2d  = (const int*)d_in[5];
    float* out = (float*)d_out;

    __half *p_x, *p_qkvw, *p_projw, *p_aoh;
    cudaGetSymbolAddress((void**)&p_x, gh_x);
    cudaGetSymbolAddress((void**)&p_qkvw, gh_qkvw);
    cudaGetSymbolAddress((void**)&p_projw, gh_projw);
    cudaGetSymbolAddress((void**)&p_aoh, g_aoh);

    cudaFuncSetAttribute(attn_mma_kernel,
                         cudaFuncAttributeMaxDynamicSharedMemorySize,
                         ATTN_SMEM_BYTES);

    // 0) setup: f32->f16 inputs + RoPE sincos table
    {
        int nx = B_ * N_ * C_ / 8;
        f2h_kernel<<<(nx + 255) / 256, 256>>>(x_t, p_x, nx);
        int nw = 3 * C_ * C_ / 8;
        f2h_kernel<<<(nw + 255) / 256, 256>>>(qkv_w, p_qkvw, nw);
        int np = C_ * C_ / 8;
        f2h_kernel<<<(np + 255) / 256, 256>>>(proj_w, p_projw, np);
        rope_tab_kernel<<<2, 256>>>();
    }
    // 1) QKV GEMM + fused bias + RoPE2D(table) + split -> fp16 q/k/v
    {
        dim3 grid((3 * C_) / 128, (B_ * N_) / 128);
        gemm_k<true><<<grid, 256>>>(p_x, p_qkvw, qkv_b, nullptr, pos2d,
                                    B_ * N_, 3 * C_, C_);
    }
    // 2) Attention (fp16 MMA, BQ=128, cp.async pipeline) -> fp16 g_aoh
    {
        dim3 grid(N_ / 128, B_ * H_);
        attn_mma_kernel<<<grid, 256, ATTN_SMEM_BYTES>>>(p_aoh);
    }
    // 3) Output projection (fp16 in, f32 out): [8192,768] x [768,768]^T
    {
        dim3 grid(C_ / 128, (B_ * N_) / 128);
        gemm_k<false><<<grid, 256>>>(p_aoh, p_projw, proj_b, out, nullptr,
                                     B_ * N_, C_, C_);
    }
}